// round 1
// baseline (speedup 1.0000x reference)
#include <cuda_runtime.h>
#include <math.h>

#define B_    2
#define S_    2048
#define HID_  4096
#define NH_   32
#define NKV_  8
#define HD_   128
#define SCALE_ 0.08838834764831845f   // 128^-0.5

// ---------------- scratch (static device globals; no runtime allocation) ----
__device__ float g_q [B_ * NH_  * S_ * HD_];   // proj Q, [B,NH,S,HD]
__device__ float g_qt[B_ * NH_  * S_ * HD_];   // rope'd Q, [B,NH,HD,S]
__device__ float g_k [B_ * NKV_ * S_ * HD_];   // proj K, [B,NKV,S,HD]
__device__ float g_kt[B_ * NKV_ * S_ * HD_];   // rope'd K, [B,NKV,HD,S]
__device__ float g_v [B_ * NKV_ * S_ * HD_];   // V, [B,NKV,S,HD]
__device__ float g_o [B_ * S_ * NH_ * HD_];    // attn out, [B,S,NH*HD]

// ---------------- SGEMM: C = A @ W^T  (A: [M,K] rm, W: [N,K] rm) ------------
// 128x128x16 tile, 256 threads, 8x8 per thread.
// HEADOUT: write C[m,n] into head layout [B][H][S][HD] (m=b*S+s, n=h*HD+d)
template <bool HEADOUT>
__global__ void __launch_bounds__(256)
sgemm_nt(const float* __restrict__ A, const float* __restrict__ W,
         float* __restrict__ C, int M, int N, int K, int H)
{
    __shared__ float As[16][132];
    __shared__ float Bs[16][132];

    const int bm = blockIdx.y, bn = blockIdx.x;
    const int tid = threadIdx.x;
    const int ty = tid >> 4, tx = tid & 15;
    const int m0 = bm * 128, n0 = bn * 128;

    const int row_l = tid >> 2;   // 0..63
    const int k4    = tid & 3;    // 0..3 (which float4 along K)

    float acc[8][8];
#pragma unroll
    for (int i = 0; i < 8; i++)
#pragma unroll
        for (int j = 0; j < 8; j++) acc[i][j] = 0.0f;

    for (int kt = 0; kt < K; kt += 16) {
#pragma unroll
        for (int u = 0; u < 2; u++) {
            int r = row_l + u * 64;
            float4 av = *(const float4*)&A[(size_t)(m0 + r) * K + kt + k4 * 4];
            As[k4 * 4 + 0][r] = av.x; As[k4 * 4 + 1][r] = av.y;
            As[k4 * 4 + 2][r] = av.z; As[k4 * 4 + 3][r] = av.w;
            float4 bv = *(const float4*)&W[(size_t)(n0 + r) * K + kt + k4 * 4];
            Bs[k4 * 4 + 0][r] = bv.x; Bs[k4 * 4 + 1][r] = bv.y;
            Bs[k4 * 4 + 2][r] = bv.z; Bs[k4 * 4 + 3][r] = bv.w;
        }
        __syncthreads();

#pragma unroll
        for (int k = 0; k < 16; k++) {
            float a[8], b[8];
            *(float4*)(a)     = *(const float4*)&As[k][ty * 4];
            *(float4*)(a + 4) = *(const float4*)&As[k][ty * 4 + 64];
            *(float4*)(b)     = *(const float4*)&Bs[k][tx * 4];
            *(float4*)(b + 4) = *(const float4*)&Bs[k][tx * 4 + 64];
#pragma unroll
            for (int i = 0; i < 8; i++)
#pragma unroll
                for (int j = 0; j < 8; j++)
                    acc[i][j] += a[i] * b[j];
        }
        __syncthreads();
    }

    // epilogue
#pragma unroll
    for (int ii = 0; ii < 2; ii++) {
#pragma unroll
        for (int i = 0; i < 4; i++) {
            int m = m0 + ty * 4 + i + ii * 64;
#pragma unroll
            for (int jj = 0; jj < 2; jj++) {
                int n = n0 + tx * 4 + jj * 64;
                float4 v = make_float4(acc[ii * 4 + i][jj * 4 + 0],
                                       acc[ii * 4 + i][jj * 4 + 1],
                                       acc[ii * 4 + i][jj * 4 + 2],
                                       acc[ii * 4 + i][jj * 4 + 3]);
                if (HEADOUT) {
                    int b  = m >> 11;         // m / S_
                    int s  = m & (S_ - 1);
                    int hh = n >> 7;          // n / HD_
                    int d  = n & (HD_ - 1);
                    *(float4*)&C[(((size_t)(b * H + hh)) * S_ + s) * HD_ + d] = v;
                } else {
                    *(float4*)&C[(size_t)m * N + n] = v;
                }
            }
        }
    }
}

// ---------------- RoPE + transpose to [B,H,HD,S] ----------------------------
__global__ void rope_transpose(const float* __restrict__ in,
                               const float* __restrict__ cs,
                               const float* __restrict__ sn,
                               float* __restrict__ out, int H)
{
    int s = blockIdx.x, h = blockIdx.y, b = blockIdx.z;
    int d = threadIdx.x;
    size_t base = ((size_t)(b * H + h) * S_ + s) * HD_;
    float x = in[base + d];
    float other = (d < 64) ? -in[base + d + 64] : in[base + d - 64];
    size_t ci = ((size_t)b * S_ + s) * HD_ + d;
    float val = x * cs[ci] + other * sn[ci];
    out[((size_t)(b * H + h) * HD_ + d) * S_ + s] = val;
}

// ---------------- flash attention (fp32, causal) ----------------------------
__device__ __forceinline__ float grpmax16(float v) {
    v = fmaxf(v, __shfl_xor_sync(0xffffffffu, v, 8));
    v = fmaxf(v, __shfl_xor_sync(0xffffffffu, v, 4));
    v = fmaxf(v, __shfl_xor_sync(0xffffffffu, v, 2));
    v = fmaxf(v, __shfl_xor_sync(0xffffffffu, v, 1));
    return v;
}
__device__ __forceinline__ float grpsum16(float v) {
    v += __shfl_xor_sync(0xffffffffu, v, 8);
    v += __shfl_xor_sync(0xffffffffu, v, 4);
    v += __shfl_xor_sync(0xffffffffu, v, 2);
    v += __shfl_xor_sync(0xffffffffu, v, 1);
    return v;
}

// smem layout (floats): Qs[128][68], Ks[128][68], Vs[64][132], Ps[64][68]
#define FA_SMEM_FLOATS (2 * 128 * 68 + 64 * 132 + 64 * 68)

__global__ void __launch_bounds__(256)
flash_kernel(const float* __restrict__ Qt, const float* __restrict__ Kt,
             const float* __restrict__ V, float* __restrict__ O)
{
    extern __shared__ float sm[];
    float* Qs = sm;                          // 128*68
    float* Ks = sm + 128 * 68;               // 128*68
    float* Vs = sm + 2 * 128 * 68;           // 64*132
    float* Ps = sm + 2 * 128 * 68 + 64 * 132;// 64*68

    const int qt  = blockIdx.x;
    const int h   = blockIdx.y;
    const int b   = blockIdx.z;
    const int kvh = h >> 2;                  // N_REP = 4
    const int tid = threadIdx.x;
    const int ty = tid >> 4, tx = tid & 15;
    const int q0 = qt * 64;

    const float* qb = Qt + (size_t)(b * NH_ + h)    * HD_ * S_;
    const float* kb = Kt + (size_t)(b * NKV_ + kvh) * HD_ * S_;
    const float* vb = V  + (size_t)(b * NKV_ + kvh) * S_ * HD_;

    // load Q tile (pre-scaled), d-major: Qs[d][q]
#pragma unroll
    for (int u = 0; u < 8; u++) {
        int idx = tid + u * 256;
        int d = idx >> 4, qc = (idx & 15) << 2;
        float4 v = *(const float4*)&qb[(size_t)d * S_ + q0 + qc];
        v.x *= SCALE_; v.y *= SCALE_; v.z *= SCALE_; v.w *= SCALE_;
        *(float4*)&Qs[d * 68 + qc] = v;
    }

    float oacc[4][8];
#pragma unroll
    for (int i = 0; i < 4; i++)
#pragma unroll
        for (int j = 0; j < 8; j++) oacc[i][j] = 0.0f;
    float mrun[4] = {-1e30f, -1e30f, -1e30f, -1e30f};
    float lrun[4] = {0.0f, 0.0f, 0.0f, 0.0f};

    for (int t = 0; t <= qt; t++) {
        const int kv0 = t * 64;
        __syncthreads();   // prev iter's Ks/Vs/Ps fully consumed
#pragma unroll
        for (int u = 0; u < 8; u++) {
            int idx = tid + u * 256;
            int d = idx >> 4, kc = (idx & 15) << 2;
            *(float4*)&Ks[d * 68 + kc] =
                *(const float4*)&kb[(size_t)d * S_ + kv0 + kc];
            int k = idx >> 5, dc = (idx & 31) << 2;
            *(float4*)&Vs[k * 132 + dc] =
                *(const float4*)&vb[(size_t)(kv0 + k) * HD_ + dc];
        }
        __syncthreads();

        // S = Q K^T tile (64x64), 4x4 per thread
        float sacc[4][4];
#pragma unroll
        for (int i = 0; i < 4; i++)
#pragma unroll
            for (int j = 0; j < 4; j++) sacc[i][j] = 0.0f;

#pragma unroll 8
        for (int d = 0; d < 128; d++) {
            float4 qa = *(const float4*)&Qs[d * 68 + (ty << 2)];
            float4 ka = *(const float4*)&Ks[d * 68 + (tx << 2)];
            float aq[4] = {qa.x, qa.y, qa.z, qa.w};
            float bk[4] = {ka.x, ka.y, ka.z, ka.w};
#pragma unroll
            for (int i = 0; i < 4; i++)
#pragma unroll
                for (int j = 0; j < 4; j++)
                    sacc[i][j] += aq[i] * bk[j];
        }

        if (t == qt) {  // diagonal tile: causal mask (kv0 == q0)
#pragma unroll
            for (int i = 0; i < 4; i++)
#pragma unroll
                for (int j = 0; j < 4; j++)
                    if ((tx << 2) + j > (ty << 2) + i) sacc[i][j] = -1e30f;
        }

        // online softmax per q-row (rows owned by the 16-lane tx group)
        float alpha[4];
#pragma unroll
        for (int i = 0; i < 4; i++) {
            float mx = fmaxf(fmaxf(sacc[i][0], sacc[i][1]),
                             fmaxf(sacc[i][2], sacc[i][3]));
            mx = grpmax16(mx);
            float mnew = fmaxf(mrun[i], mx);
            float al = __expf(mrun[i] - mnew);
            float ssum = 0.0f;
#pragma unroll
            for (int j = 0; j < 4; j++) {
                float p = __expf(sacc[i][j] - mnew);
                sacc[i][j] = p;
                ssum += p;
            }
            ssum = grpsum16(ssum);
            lrun[i] = lrun[i] * al + ssum;
            mrun[i] = mnew;
            alpha[i] = al;
            *(float4*)&Ps[((ty << 2) + i) * 68 + (tx << 2)] =
                make_float4(sacc[i][0], sacc[i][1], sacc[i][2], sacc[i][3]);
        }
#pragma unroll
        for (int i = 0; i < 4; i++)
#pragma unroll
            for (int j = 0; j < 8; j++) oacc[i][j] *= alpha[i];

        __syncthreads();

        // O += P V  (thread: 4 q-rows x 8 d-cols)
#pragma unroll 4
        for (int k = 0; k < 64; k++) {
            float4 v0 = *(const float4*)&Vs[k * 132 + (tx << 3)];
            float4 v1 = *(const float4*)&Vs[k * 132 + (tx << 3) + 4];
#pragma unroll
            for (int i = 0; i < 4; i++) {
                float p = Ps[((ty << 2) + i) * 68 + k];
                oacc[i][0] += p * v0.x; oacc[i][1] += p * v0.y;
                oacc[i][2] += p * v0.z; oacc[i][3] += p * v0.w;
                oacc[i][4] += p * v1.x; oacc[i][5] += p * v1.y;
                oacc[i][6] += p * v1.z; oacc[i][7] += p * v1.w;
            }
        }
    }

    // write O: [B, S, NH*HD]
#pragma unroll
    for (int i = 0; i < 4; i++) {
        float inv = 1.0f / lrun[i];
        int q = q0 + (ty << 2) + i;
        float* dst = O + ((size_t)(b * S_ + q)) * (NH_ * HD_) + h * HD_ + (tx << 3);
        *(float4*)dst = make_float4(oacc[i][0] * inv, oacc[i][1] * inv,
                                    oacc[i][2] * inv, oacc[i][3] * inv);
        *(float4*)(dst + 4) = make_float4(oacc[i][4] * inv, oacc[i][5] * inv,
                                          oacc[i][6] * inv, oacc[i][7] * inv);
    }
}

// ---------------- launch -----------------------------------------------------
extern "C" void kernel_launch(void* const* d_in, const int* in_sizes, int n_in,
                              void* d_out, int out_size)
{
    (void)in_sizes; (void)n_in; (void)out_size;
    const float* hs = (const float*)d_in[0];
    const float* cs = (const float*)d_in[1];
    const float* sn = (const float*)d_in[2];
    // d_in[3] attention_mask: causal -1e9 triu, replicated analytically
    const float* Wq = (const float*)d_in[4];
    const float* Wk = (const float*)d_in[5];
    const float* Wv = (const float*)d_in[6];
    const float* Wo = (const float*)d_in[7];
    float* out = (float*)d_out;

    float *q, *qt, *k, *kt, *v, *o;
    cudaGetSymbolAddress((void**)&q,  g_q);
    cudaGetSymbolAddress((void**)&qt, g_qt);
    cudaGetSymbolAddress((void**)&k,  g_k);
    cudaGetSymbolAddress((void**)&kt, g_kt);
    cudaGetSymbolAddress((void**)&v,  g_v);
    cudaGetSymbolAddress((void**)&o,  g_o);

    dim3 blk(256);
    // projections (M = B*S = 4096, K = HID = 4096)
    sgemm_nt<true><<<dim3(32, 32), blk>>>(hs, Wq, q, 4096, 4096, 4096, NH_);
    sgemm_nt<true><<<dim3(8, 32),  blk>>>(hs, Wk, k, 4096, 1024, 4096, NKV_);
    sgemm_nt<true><<<dim3(8, 32),  blk>>>(hs, Wv, v, 4096, 1024, 4096, NKV_);

    rope_transpose<<<dim3(S_, NH_, B_),  128>>>(q, cs, sn, qt, NH_);
    rope_transpose<<<dim3(S_, NKV_, B_), 128>>>(k, cs, sn, kt, NKV_);

    size_t smem = FA_SMEM_FLOATS * sizeof(float);   // ~118 KB
    cudaFuncSetAttribute(flash_kernel,
                         cudaFuncAttributeMaxDynamicSharedMemorySize, (int)smem);
    flash_kernel<<<dim3(S_ / 64, NH_, B_), 256, smem>>>(qt, kt, v, o);

    // output projection
    sgemm_nt<false><<<dim3(32, 32), blk>>>(o, Wo, out, 4096, 4096, 4096, 0);
}

// round 3
// speedup vs baseline: 1.6429x; 1.6429x over previous
#include <cuda_runtime.h>
#include <cuda_fp16.h>
#include <math.h>
#include <stdint.h>

#define B_    2
#define S_    2048
#define HID_  4096
#define NH_   32
#define NKV_  8
#define HD_   128
#define SCALE_ 0.08838834764831845f   // 128^-0.5

// ======================= PTX helpers ========================================
__device__ __forceinline__ uint32_t smem_u32(const void* p) {
    uint32_t a;
    asm("{ .reg .u64 t; cvta.to.shared.u64 t, %1; cvt.u32.u64 %0, t; }"
        : "=r"(a) : "l"(p));
    return a;
}
#define CP_ASYNC16(dst, src) \
    asm volatile("cp.async.cg.shared.global [%0], [%1], 16;" :: "r"(dst), "l"(src))
#define CP_COMMIT() asm volatile("cp.async.commit_group;" ::: "memory")
#define CP_WAIT(n)  asm volatile("cp.async.wait_group %0;" :: "n"(n) : "memory")

#define LDSM4(r0, r1, r2, r3, a)                                              \
    asm volatile("ldmatrix.sync.aligned.m8n8.x4.shared.b16 {%0,%1,%2,%3}, [%4];" \
        : "=r"(r0), "=r"(r1), "=r"(r2), "=r"(r3) : "r"(a))

#define MMA16816(c, av, bv)                                                   \
    asm volatile("mma.sync.aligned.m16n8k16.row.col.f32.f16.f16.f32 "         \
        "{%0,%1,%2,%3}, {%4,%5,%6,%7}, {%8,%9}, {%0,%1,%2,%3};"               \
        : "+f"((c)[0]), "+f"((c)[1]), "+f"((c)[2]), "+f"((c)[3])              \
        : "r"((av)[0]), "r"((av)[1]), "r"((av)[2]), "r"((av)[3]),             \
          "r"((bv)[0]), "r"((bv)[1]))

// ======================= scratch ============================================
__device__ float g_q [B_ * NH_  * S_ * HD_];
__device__ float g_qt[B_ * NH_  * S_ * HD_];
__device__ float g_k [B_ * NKV_ * S_ * HD_];
__device__ float g_kt[B_ * NKV_ * S_ * HD_];
__device__ float g_v [B_ * NKV_ * S_ * HD_];

__device__ __half g_hs_h[4096 * 4096], g_hs_l[4096 * 4096];
__device__ __half g_wq_h[4096 * 4096], g_wq_l[4096 * 4096];
__device__ __half g_wk_h[1024 * 4096], g_wk_l[1024 * 4096];
__device__ __half g_wv_h[1024 * 4096], g_wv_l[1024 * 4096];
__device__ __half g_wo_h[4096 * 4096], g_wo_l[4096 * 4096];
__device__ __half g_o_h [4096 * 4096], g_o_l [4096 * 4096];

// ======================= split fp32 -> fp16 hi/lo ============================
__global__ void __launch_bounds__(256)
split_hilo(const float* __restrict__ x, __half* __restrict__ hi,
           __half* __restrict__ lo, int n4)
{
    int i = blockIdx.x * blockDim.x + threadIdx.x;
    if (i >= n4) return;
    float4 v = ((const float4*)x)[i];
    __half h0 = __float2half(v.x), h1 = __float2half(v.y);
    __half h2 = __float2half(v.z), h3 = __float2half(v.w);
    __half l0 = __float2half(v.x - __half2float(h0));
    __half l1 = __float2half(v.y - __half2float(h1));
    __half l2 = __float2half(v.z - __half2float(h2));
    __half l3 = __float2half(v.w - __half2float(h3));
    ((__half2*)hi)[2 * i + 0] = __halves2half2(h0, h1);
    ((__half2*)hi)[2 * i + 1] = __halves2half2(h2, h3);
    ((__half2*)lo)[2 * i + 0] = __halves2half2(l0, l1);
    ((__half2*)lo)[2 * i + 1] = __halves2half2(l2, l3);
}

// ======================= HMMA fp16x3 GEMM ===================================
// C[M,N] = Ah@Bh^T + Ah@Bl^T + Al@Bh^T   (A [M,K], B [N,K] row-major, K-contig)
// 128x128 CTA tile, K-tile 32, 8 warps (warp tile 32x64), double buffered.
#define ROWH  40                      // smem row stride in halfs (80 B)
#define TILEB (128 * ROWH * 2)        // 10240 B per operand tile
#define STAGEB (4 * TILEB)            // 40960 B per stage
#define GSMEM_BYTES (2 * STAGEB)      // 81920 B

template <bool HEADOUT>
__global__ void __launch_bounds__(256)
gemm3_h16(const __half* __restrict__ Ah, const __half* __restrict__ Al,
          const __half* __restrict__ Bh, const __half* __restrict__ Bl,
          float* __restrict__ C, int K, int Ntot, int H)
{
    extern __shared__ char smem[];
    const uint32_t sbase = smem_u32(smem);
    const int tid  = threadIdx.x;
    const int wid  = tid >> 5;
    const int lane = tid & 31;
    const int m0 = blockIdx.y * 128;
    const int n0 = blockIdx.x * 128;
    const int wm0 = (wid & 3) * 32;     // warp m offset (32 rows)
    const int wn0 = (wid >> 2) * 64;    // warp n offset (64 cols)
    const int niter = K >> 5;           // K / 32

    float acc[2][8][4];
#pragma unroll
    for (int i = 0; i < 2; i++)
#pragma unroll
        for (int j = 0; j < 8; j++)
#pragma unroll
            for (int r = 0; r < 4; r++) acc[i][j][r] = 0.0f;

    auto load_stage = [&](int it, int st) {
        uint32_t base = sbase + st * STAGEB;
        int kt = it << 5;
#pragma unroll
        for (int tile = 0; tile < 4; tile++) {
            const __half* src = (tile == 0) ? Ah : (tile == 1) ? Al
                              : (tile == 2) ? Bh : Bl;
            int r0 = (tile < 2) ? m0 : n0;
#pragma unroll
            for (int rc = 0; rc < 2; rc++) {
                int c = tid * 2 + rc;             // 0..511
                int row = c >> 2, seg = c & 3;
                uint32_t dst = base + tile * TILEB + row * 80 + seg * 16;
                CP_ASYNC16(dst, src + (size_t)(r0 + row) * K + kt + seg * 8);
            }
        }
        CP_COMMIT();
    };

    // per-lane ldmatrix byte offsets (relative to operand tile base)
    const uint32_t a_off = (uint32_t)(wm0 + (lane & 15)) * 80 + (lane >> 4) * 16;
    const uint32_t b_off = (uint32_t)(wn0 + ((lane >> 4) & 1) * 8 + (lane & 7)) * 80
                         + ((lane >> 3) & 1) * 16;

    load_stage(0, 0);
    for (int it = 0; it < niter; it++) {
        if (it + 1 < niter) { load_stage(it + 1, (it + 1) & 1); CP_WAIT(1); }
        else                { CP_WAIT(0); }
        __syncthreads();

        uint32_t tb = sbase + (it & 1) * STAGEB;
        uint32_t As_h = tb, As_l = tb + TILEB;
        uint32_t Bs_h = tb + 2 * TILEB, Bs_l = tb + 3 * TILEB;

#pragma unroll
        for (int k16 = 0; k16 < 2; k16++) {
            uint32_t kb = k16 * 32;   // 16 halfs = 32 B
            uint32_t ah[2][4], al[2][4], bh[8][2], bl[8][2];
#pragma unroll
            for (int mt = 0; mt < 2; mt++) {
                uint32_t o = a_off + mt * 16 * 80 + kb;
                LDSM4(ah[mt][0], ah[mt][1], ah[mt][2], ah[mt][3], As_h + o);
                LDSM4(al[mt][0], al[mt][1], al[mt][2], al[mt][3], As_l + o);
            }
#pragma unroll
            for (int np = 0; np < 4; np++) {
                uint32_t o = b_off + np * 16 * 80 + kb;
                LDSM4(bh[2*np][0], bh[2*np][1], bh[2*np+1][0], bh[2*np+1][1], Bs_h + o);
                LDSM4(bl[2*np][0], bl[2*np][1], bl[2*np+1][0], bl[2*np+1][1], Bs_l + o);
            }
#pragma unroll
            for (int mt = 0; mt < 2; mt++)
#pragma unroll
                for (int nt = 0; nt < 8; nt++) {
                    MMA16816(acc[mt][nt], ah[mt], bh[nt]);
                    MMA16816(acc[mt][nt], ah[mt], bl[nt]);
                    MMA16816(acc[mt][nt], al[mt], bh[nt]);
                }
        }
        __syncthreads();
    }

    // epilogue
#pragma unroll
    for (int mt = 0; mt < 2; mt++) {
        int r = m0 + wm0 + mt * 16 + (lane >> 2);
#pragma unroll
        for (int nt = 0; nt < 8; nt++) {
            int cl = wn0 + nt * 8 + (lane & 3) * 2;   // local col within block
            if (HEADOUT) {
                int b  = r >> 11;
                int s  = r & (S_ - 1);
                int hh = n0 >> 7;
                float* base = C + (((size_t)(b * H + hh)) * S_ + s) * HD_;
                *(float2*)(base + cl) = make_float2(acc[mt][nt][0], acc[mt][nt][1]);
                float* base2 = C + (((size_t)(b * H + hh)) * S_ + (s + 8)) * HD_;
                // r+8 shares b,hh (block rows never straddle batch: 128 | 2048)
                *(float2*)(base2 + cl) = make_float2(acc[mt][nt][2], acc[mt][nt][3]);
            } else {
                float* p0 = C + (size_t)r * Ntot + n0 + cl;
                *(float2*)p0 = make_float2(acc[mt][nt][0], acc[mt][nt][1]);
                float* p1 = C + (size_t)(r + 8) * Ntot + n0 + cl;
                *(float2*)p1 = make_float2(acc[mt][nt][2], acc[mt][nt][3]);
            }
        }
    }
}

// ======================= RoPE + transpose to [B,H,HD,S] ======================
__global__ void rope_transpose(const float* __restrict__ in,
                               const float* __restrict__ cs,
                               const float* __restrict__ sn,
                               float* __restrict__ out, int H)
{
    int s = blockIdx.x, h = blockIdx.y, b = blockIdx.z;
    int d = threadIdx.x;
    size_t base = ((size_t)(b * H + h) * S_ + s) * HD_;
    float x = in[base + d];
    float other = (d < 64) ? -in[base + d + 64] : in[base + d - 64];
    size_t ci = ((size_t)b * S_ + s) * HD_ + d;
    float val = x * cs[ci] + other * sn[ci];
    out[((size_t)(b * H + h) * HD_ + d) * S_ + s] = val;
}

// ======================= flash attention (fp32, causal) ======================
__device__ __forceinline__ float grpmax16(float v) {
    v = fmaxf(v, __shfl_xor_sync(0xffffffffu, v, 8));
    v = fmaxf(v, __shfl_xor_sync(0xffffffffu, v, 4));
    v = fmaxf(v, __shfl_xor_sync(0xffffffffu, v, 2));
    v = fmaxf(v, __shfl_xor_sync(0xffffffffu, v, 1));
    return v;
}
__device__ __forceinline__ float grpsum16(float v) {
    v += __shfl_xor_sync(0xffffffffu, v, 8);
    v += __shfl_xor_sync(0xffffffffu, v, 4);
    v += __shfl_xor_sync(0xffffffffu, v, 2);
    v += __shfl_xor_sync(0xffffffffu, v, 1);
    return v;
}

#define FA_SMEM_FLOATS (2 * 128 * 68 + 64 * 132 + 64 * 68)

__global__ void __launch_bounds__(256)
flash_kernel(const float* __restrict__ Qt, const float* __restrict__ Kt,
             const float* __restrict__ V,
             __half* __restrict__ Oh, __half* __restrict__ Ol)
{
    extern __shared__ float sm[];
    float* Qs = sm;
    float* Ks = sm + 128 * 68;
    float* Vs = sm + 2 * 128 * 68;
    float* Ps = sm + 2 * 128 * 68 + 64 * 132;

    const int qt  = blockIdx.x;
    const int h   = blockIdx.y;
    const int b   = blockIdx.z;
    const int kvh = h >> 2;
    const int tid = threadIdx.x;
    const int ty = tid >> 4, tx = tid & 15;
    const int q0 = qt * 64;

    const float* qb = Qt + (size_t)(b * NH_ + h)    * HD_ * S_;
    const float* kb = Kt + (size_t)(b * NKV_ + kvh) * HD_ * S_;
    const float* vb = V  + (size_t)(b * NKV_ + kvh) * S_ * HD_;

#pragma unroll
    for (int u = 0; u < 8; u++) {
        int idx = tid + u * 256;
        int d = idx >> 4, qc = (idx & 15) << 2;
        float4 v = *(const float4*)&qb[(size_t)d * S_ + q0 + qc];
        v.x *= SCALE_; v.y *= SCALE_; v.z *= SCALE_; v.w *= SCALE_;
        *(float4*)&Qs[d * 68 + qc] = v;
    }

    float oacc[4][8];
#pragma unroll
    for (int i = 0; i < 4; i++)
#pragma unroll
        for (int j = 0; j < 8; j++) oacc[i][j] = 0.0f;
    float mrun[4] = {-1e30f, -1e30f, -1e30f, -1e30f};
    float lrun[4] = {0.0f, 0.0f, 0.0f, 0.0f};

    for (int t = 0; t <= qt; t++) {
        const int kv0 = t * 64;
        __syncthreads();
#pragma unroll
        for (int u = 0; u < 8; u++) {
            int idx = tid + u * 256;
            int d = idx >> 4, kc = (idx & 15) << 2;
            *(float4*)&Ks[d * 68 + kc] =
                *(const float4*)&kb[(size_t)d * S_ + kv0 + kc];
            int k = idx >> 5, dc = (idx & 31) << 2;
            *(float4*)&Vs[k * 132 + dc] =
                *(const float4*)&vb[(size_t)(kv0 + k) * HD_ + dc];
        }
        __syncthreads();

        float sacc[4][4];
#pragma unroll
        for (int i = 0; i < 4; i++)
#pragma unroll
            for (int j = 0; j < 4; j++) sacc[i][j] = 0.0f;

#pragma unroll 8
        for (int d = 0; d < 128; d++) {
            float4 qa = *(const float4*)&Qs[d * 68 + (ty << 2)];
            float4 ka = *(const float4*)&Ks[d * 68 + (tx << 2)];
            float aq[4] = {qa.x, qa.y, qa.z, qa.w};
            float bk[4] = {ka.x, ka.y, ka.z, ka.w};
#pragma unroll
            for (int i = 0; i < 4; i++)
#pragma unroll
                for (int j = 0; j < 4; j++)
                    sacc[i][j] += aq[i] * bk[j];
        }

        if (t == qt) {
#pragma unroll
            for (int i = 0; i < 4; i++)
#pragma unroll
                for (int j = 0; j < 4; j++)
                    if ((tx << 2) + j > (ty << 2) + i) sacc[i][j] = -1e30f;
        }

        float alpha[4];
#pragma unroll
        for (int i = 0; i < 4; i++) {
            float mx = fmaxf(fmaxf(sacc[i][0], sacc[i][1]),
                             fmaxf(sacc[i][2], sacc[i][3]));
            mx = grpmax16(mx);
            float mnew = fmaxf(mrun[i], mx);
            float al = __expf(mrun[i] - mnew);
            float ssum = 0.0f;
#pragma unroll
            for (int j = 0; j < 4; j++) {
                float p = __expf(sacc[i][j] - mnew);
                sacc[i][j] = p;
                ssum += p;
            }
            ssum = grpsum16(ssum);
            lrun[i] = lrun[i] * al + ssum;
            mrun[i] = mnew;
            alpha[i] = al;
            *(float4*)&Ps[((ty << 2) + i) * 68 + (tx << 2)] =
                make_float4(sacc[i][0], sacc[i][1], sacc[i][2], sacc[i][3]);
        }
#pragma unroll
        for (int i = 0; i < 4; i++)
#pragma unroll
            for (int j = 0; j < 8; j++) oacc[i][j] *= alpha[i];

        __syncthreads();

#pragma unroll 4
        for (int k = 0; k < 64; k++) {
            float4 v0 = *(const float4*)&Vs[k * 132 + (tx << 3)];
            float4 v1 = *(const float4*)&Vs[k * 132 + (tx << 3) + 4];
#pragma unroll
            for (int i = 0; i < 4; i++) {
                float p = Ps[((ty << 2) + i) * 68 + k];
                oacc[i][0] += p * v0.x; oacc[i][1] += p * v0.y;
                oacc[i][2] += p * v0.z; oacc[i][3] += p * v0.w;
                oacc[i][4] += p * v1.x; oacc[i][5] += p * v1.y;
                oacc[i][6] += p * v1.z; oacc[i][7] += p * v1.w;
            }
        }
    }

    // write O split to fp16 hi/lo, layout [B*S, NH*HD]
#pragma unroll
    for (int i = 0; i < 4; i++) {
        float inv = 1.0f / lrun[i];
        int q = q0 + (ty << 2) + i;
        size_t base = ((size_t)(b * S_ + q)) * (NH_ * HD_) + h * HD_ + (tx << 3);
        __align__(16) __half hv[8];
        __align__(16) __half lv[8];
#pragma unroll
        for (int j = 0; j < 8; j++) {
            float f = oacc[i][j] * inv;
            __half hh = __float2half(f);
            hv[j] = hh;
            lv[j] = __float2half(f - __half2float(hh));
        }
        *(uint4*)&Oh[base] = *(const uint4*)hv;
        *(uint4*)&Ol[base] = *(const uint4*)lv;
    }
}

// ======================= launch ==============================================
extern "C" void kernel_launch(void* const* d_in, const int* in_sizes, int n_in,
                              void* d_out, int out_size)
{
    (void)in_sizes; (void)n_in; (void)out_size;
    const float* hs = (const float*)d_in[0];
    const float* cs = (const float*)d_in[1];
    const float* sn = (const float*)d_in[2];
    const float* Wq = (const float*)d_in[4];
    const float* Wk = (const float*)d_in[5];
    const float* Wv = (const float*)d_in[6];
    const float* Wo = (const float*)d_in[7];
    float* out = (float*)d_out;

    float *q, *qt, *k, *kt, *v;
    cudaGetSymbolAddress((void**)&q,  g_q);
    cudaGetSymbolAddress((void**)&qt, g_qt);
    cudaGetSymbolAddress((void**)&k,  g_k);
    cudaGetSymbolAddress((void**)&kt, g_kt);
    cudaGetSymbolAddress((void**)&v,  g_v);

    __half *hsh, *hsl, *wqh, *wql, *wkh, *wkl, *wvh, *wvl, *woh, *wol, *oh, *ol;
    cudaGetSymbolAddress((void**)&hsh, g_hs_h); cudaGetSymbolAddress((void**)&hsl, g_hs_l);
    cudaGetSymbolAddress((void**)&wqh, g_wq_h); cudaGetSymbolAddress((void**)&wql, g_wq_l);
    cudaGetSymbolAddress((void**)&wkh, g_wk_h); cudaGetSymbolAddress((void**)&wkl, g_wk_l);
    cudaGetSymbolAddress((void**)&wvh, g_wv_h); cudaGetSymbolAddress((void**)&wvl, g_wv_l);
    cudaGetSymbolAddress((void**)&woh, g_wo_h); cudaGetSymbolAddress((void**)&wol, g_wo_l);
    cudaGetSymbolAddress((void**)&oh,  g_o_h);  cudaGetSymbolAddress((void**)&ol,  g_o_l);

    const int n_big = 4096 * 4096 / 4, n_sm = 1024 * 4096 / 4;
    split_hilo<<<(n_big + 255) / 256, 256>>>(hs, hsh, hsl, n_big);
    split_hilo<<<(n_big + 255) / 256, 256>>>(Wq, wqh, wql, n_big);
    split_hilo<<<(n_sm + 255) / 256, 256>>>(Wk, wkh, wkl, n_sm);
    split_hilo<<<(n_sm + 255) / 256, 256>>>(Wv, wvh, wvl, n_sm);
    split_hilo<<<(n_big + 255) / 256, 256>>>(Wo, woh, wol, n_big);

    cudaFuncSetAttribute(gemm3_h16<true>,
                         cudaFuncAttributeMaxDynamicSharedMemorySize, GSMEM_BYTES);
    cudaFuncSetAttribute(gemm3_h16<false>,
                         cudaFuncAttributeMaxDynamicSharedMemorySize, GSMEM_BYTES);

    gemm3_h16<true><<<dim3(32, 32), 256, GSMEM_BYTES>>>(hsh, hsl, wqh, wql, q, 4096, 4096, NH_);
    gemm3_h16<true><<<dim3(8, 32),  256, GSMEM_BYTES>>>(hsh, hsl, wkh, wkl, k, 4096, 1024, NKV_);
    gemm3_h16<true><<<dim3(8, 32),  256, GSMEM_BYTES>>>(hsh, hsl, wvh, wvl, v, 4096, 1024, NKV_);

    rope_transpose<<<dim3(S_, NH_, B_),  128>>>(q, cs, sn, qt, NH_);
    rope_transpose<<<dim3(S_, NKV_, B_), 128>>>(k, cs, sn, kt, NKV_);

    size_t fsmem = FA_SMEM_FLOATS * sizeof(float);
    cudaFuncSetAttribute(flash_kernel,
                         cudaFuncAttributeMaxDynamicSharedMemorySize, (int)fsmem);
    flash_kernel<<<dim3(S_ / 64, NH_, B_), 256, fsmem>>>(qt, kt, v, oh, ol);

    gemm3_h16<false><<<dim3(32, 32), 256, GSMEM_BYTES>>>(oh, ol, woh, wol, out, 4096, 4096, 0);
}

// round 4
// speedup vs baseline: 2.0968x; 1.2763x over previous
#include <cuda_runtime.h>
#include <cuda_fp16.h>
#include <math.h>
#include <stdint.h>

#define B_    2
#define S_    2048
#define HID_  4096
#define NH_   32
#define NKV_  8
#define HD_   128
#define SCALE_ 0.08838834764831845f   // 128^-0.5

// ======================= PTX helpers ========================================
__device__ __forceinline__ uint32_t smem_u32(const void* p) {
    uint32_t a;
    asm("{ .reg .u64 t; cvta.to.shared.u64 t, %1; cvt.u32.u64 %0, t; }"
        : "=r"(a) : "l"(p));
    return a;
}
#define CP_ASYNC16(dst, src) \
    asm volatile("cp.async.cg.shared.global [%0], [%1], 16;" :: "r"(dst), "l"(src))
#define CP_COMMIT() asm volatile("cp.async.commit_group;" ::: "memory")
#define CP_WAIT(n)  asm volatile("cp.async.wait_group %0;" :: "n"(n) : "memory")

#define LDSM4(r0, r1, r2, r3, a)                                              \
    asm volatile("ldmatrix.sync.aligned.m8n8.x4.shared.b16 {%0,%1,%2,%3}, [%4];" \
        : "=r"(r0), "=r"(r1), "=r"(r2), "=r"(r3) : "r"(a))
#define LDSM4T(r0, r1, r2, r3, a)                                             \
    asm volatile("ldmatrix.sync.aligned.m8n8.x4.trans.shared.b16 {%0,%1,%2,%3}, [%4];" \
        : "=r"(r0), "=r"(r1), "=r"(r2), "=r"(r3) : "r"(a))

#define MMA16816(c, av, bv)                                                   \
    asm volatile("mma.sync.aligned.m16n8k16.row.col.f32.f16.f16.f32 "         \
        "{%0,%1,%2,%3}, {%4,%5,%6,%7}, {%8,%9}, {%0,%1,%2,%3};"               \
        : "+f"((c)[0]), "+f"((c)[1]), "+f"((c)[2]), "+f"((c)[3])              \
        : "r"((av)[0]), "r"((av)[1]), "r"((av)[2]), "r"((av)[3]),             \
          "r"((bv)[0]), "r"((bv)[1]))

// ======================= scratch ============================================
__device__ float g_q [B_ * NH_  * S_ * HD_];
__device__ float g_k [B_ * NKV_ * S_ * HD_];
__device__ float g_v [B_ * NKV_ * S_ * HD_];

__device__ __half g_hs_h[4096 * 4096], g_hs_l[4096 * 4096];
__device__ __half g_wq_h[4096 * 4096], g_wq_l[4096 * 4096];
__device__ __half g_wk_h[1024 * 4096], g_wk_l[1024 * 4096];
__device__ __half g_wv_h[1024 * 4096], g_wv_l[1024 * 4096];
__device__ __half g_wo_h[4096 * 4096], g_wo_l[4096 * 4096];
__device__ __half g_o_h [4096 * 4096], g_o_l [4096 * 4096];
__device__ __half g_qh[B_ * NH_  * S_ * HD_], g_ql[B_ * NH_  * S_ * HD_];
__device__ __half g_kh[B_ * NKV_ * S_ * HD_], g_kl[B_ * NKV_ * S_ * HD_];
__device__ __half g_vh[B_ * NKV_ * S_ * HD_], g_vl[B_ * NKV_ * S_ * HD_];

// ======================= split fp32 -> fp16 hi/lo ============================
__global__ void __launch_bounds__(256)
split_hilo(const float* __restrict__ x, __half* __restrict__ hi,
           __half* __restrict__ lo, int n4)
{
    int i = blockIdx.x * blockDim.x + threadIdx.x;
    if (i >= n4) return;
    float4 v = ((const float4*)x)[i];
    __half h0 = __float2half(v.x), h1 = __float2half(v.y);
    __half h2 = __float2half(v.z), h3 = __float2half(v.w);
    __half l0 = __float2half(v.x - __half2float(h0));
    __half l1 = __float2half(v.y - __half2float(h1));
    __half l2 = __float2half(v.z - __half2float(h2));
    __half l3 = __float2half(v.w - __half2float(h3));
    ((__half2*)hi)[2 * i + 0] = __halves2half2(h0, h1);
    ((__half2*)hi)[2 * i + 1] = __halves2half2(h2, h3);
    ((__half2*)lo)[2 * i + 0] = __halves2half2(l0, l1);
    ((__half2*)lo)[2 * i + 1] = __halves2half2(l2, l3);
}

// ======================= HMMA fp16x3 GEMM (3-stage) ==========================
#define ROWH  40
#define TILEB (128 * ROWH * 2)        // 10240 B
#define STAGEB (4 * TILEB)            // 40960 B
#define GSMEM_BYTES (3 * STAGEB)      // 122880 B

template <bool HEADOUT>
__global__ void __launch_bounds__(256)
gemm3_h16(const __half* __restrict__ Ah, const __half* __restrict__ Al,
          const __half* __restrict__ Bh, const __half* __restrict__ Bl,
          float* __restrict__ C, int K, int Ntot, int H)
{
    extern __shared__ char smem[];
    const uint32_t sbase = smem_u32(smem);
    const int tid  = threadIdx.x;
    const int wid  = tid >> 5;
    const int lane = tid & 31;
    const int m0 = blockIdx.y * 128;
    const int n0 = blockIdx.x * 128;
    const int wm0 = (wid & 3) * 32;
    const int wn0 = (wid >> 2) * 64;
    const int niter = K >> 5;

    float acc[2][8][4];
#pragma unroll
    for (int i = 0; i < 2; i++)
#pragma unroll
        for (int j = 0; j < 8; j++)
#pragma unroll
            for (int r = 0; r < 4; r++) acc[i][j][r] = 0.0f;

    auto load_stage = [&](int it, int st) {
        uint32_t base = sbase + st * STAGEB;
        int kt = it << 5;
#pragma unroll
        for (int tile = 0; tile < 4; tile++) {
            const __half* src = (tile == 0) ? Ah : (tile == 1) ? Al
                              : (tile == 2) ? Bh : Bl;
            int r0 = (tile < 2) ? m0 : n0;
#pragma unroll
            for (int rc = 0; rc < 2; rc++) {
                int c = tid * 2 + rc;
                int row = c >> 2, seg = c & 3;
                uint32_t dst = base + tile * TILEB + row * 80 + seg * 16;
                CP_ASYNC16(dst, src + (size_t)(r0 + row) * K + kt + seg * 8);
            }
        }
        CP_COMMIT();
    };

    const uint32_t a_off = (uint32_t)(wm0 + (lane & 15)) * 80 + (lane >> 4) * 16;
    const uint32_t b_off = (uint32_t)(wn0 + ((lane >> 4) & 1) * 8 + (lane & 7)) * 80
                         + ((lane >> 3) & 1) * 16;

    load_stage(0, 0);
    if (niter > 1) load_stage(1, 1);
    for (int it = 0; it < niter; it++) {
        if (it + 2 < niter) { load_stage(it + 2, (it + 2) % 3); CP_WAIT(2); }
        else if (it + 1 < niter) { CP_WAIT(1); }
        else { CP_WAIT(0); }
        __syncthreads();

        uint32_t tb = sbase + (it % 3) * STAGEB;
        uint32_t As_h = tb, As_l = tb + TILEB;
        uint32_t Bs_h = tb + 2 * TILEB, Bs_l = tb + 3 * TILEB;

#pragma unroll
        for (int k16 = 0; k16 < 2; k16++) {
            uint32_t kb = k16 * 32;
            uint32_t ah[2][4], al[2][4], bh[8][2], bl[8][2];
#pragma unroll
            for (int mt = 0; mt < 2; mt++) {
                uint32_t o = a_off + mt * 16 * 80 + kb;
                LDSM4(ah[mt][0], ah[mt][1], ah[mt][2], ah[mt][3], As_h + o);
                LDSM4(al[mt][0], al[mt][1], al[mt][2], al[mt][3], As_l + o);
            }
#pragma unroll
            for (int np = 0; np < 4; np++) {
                uint32_t o = b_off + np * 16 * 80 + kb;
                LDSM4(bh[2*np][0], bh[2*np][1], bh[2*np+1][0], bh[2*np+1][1], Bs_h + o);
                LDSM4(bl[2*np][0], bl[2*np][1], bl[2*np+1][0], bl[2*np+1][1], Bs_l + o);
            }
#pragma unroll
            for (int mt = 0; mt < 2; mt++)
#pragma unroll
                for (int nt = 0; nt < 8; nt++) {
                    MMA16816(acc[mt][nt], ah[mt], bh[nt]);
                    MMA16816(acc[mt][nt], ah[mt], bl[nt]);
                    MMA16816(acc[mt][nt], al[mt], bh[nt]);
                }
        }
        __syncthreads();
    }

#pragma unroll
    for (int mt = 0; mt < 2; mt++) {
        int r = m0 + wm0 + mt * 16 + (lane >> 2);
#pragma unroll
        for (int nt = 0; nt < 8; nt++) {
            int cl = wn0 + nt * 8 + (lane & 3) * 2;
            if (HEADOUT) {
                int b  = r >> 11;
                int s  = r & (S_ - 1);
                int hh = n0 >> 7;
                float* base = C + (((size_t)(b * H + hh)) * S_ + s) * HD_;
                *(float2*)(base + cl) = make_float2(acc[mt][nt][0], acc[mt][nt][1]);
                float* base2 = C + (((size_t)(b * H + hh)) * S_ + (s + 8)) * HD_;
                *(float2*)(base2 + cl) = make_float2(acc[mt][nt][2], acc[mt][nt][3]);
            } else {
                float* p0 = C + (size_t)r * Ntot + n0 + cl;
                *(float2*)p0 = make_float2(acc[mt][nt][0], acc[mt][nt][1]);
                float* p1 = C + (size_t)(r + 8) * Ntot + n0 + cl;
                *(float2*)p1 = make_float2(acc[mt][nt][2], acc[mt][nt][3]);
            }
        }
    }
}

// ======================= RoPE -> fp16 hi/lo (same layout) ====================
__global__ void rope_split(const float* __restrict__ in,
                           const float* __restrict__ cs,
                           const float* __restrict__ sn,
                           __half* __restrict__ oh, __half* __restrict__ ol, int H)
{
    int s = blockIdx.x, h = blockIdx.y, b = blockIdx.z;
    int d = threadIdx.x;
    size_t base = ((size_t)(b * H + h) * S_ + s) * HD_;
    float x = in[base + d];
    float other = (d < 64) ? -in[base + d + 64] : in[base + d - 64];
    size_t ci = ((size_t)b * S_ + s) * HD_ + d;
    float val = x * cs[ci] + other * sn[ci];
    __half hh = __float2half(val);
    oh[base + d] = hh;
    ol[base + d] = __float2half(val - __half2float(hh));
}

// ======================= HMMA flash attention ================================
// BQ=64 (4 warps x 16 rows), BK=64, fp16 x3 split, fp32 accum, causal.
#define FROWB 272                      // 136 halfs row stride
#define FTILE (64 * FROWB)             // 17408 B
#define FSMEM_BYTES ((2 + 8) * FTILE)  // Q hi/lo + 2 stages x (Kh,Kl,Vh,Vl)

__global__ void __launch_bounds__(128)
flash16(const __half* __restrict__ Qh, const __half* __restrict__ Ql,
        const __half* __restrict__ Kh, const __half* __restrict__ Kl,
        const __half* __restrict__ Vh, const __half* __restrict__ Vl,
        __half* __restrict__ Oh, __half* __restrict__ Ol)
{
    extern __shared__ char smc[];
    const uint32_t sb = smem_u32(smc);
    const int qt = blockIdx.x, h = blockIdx.y, b = blockIdx.z;
    const int kvh = h >> 2;
    const int tid = threadIdx.x, wid = tid >> 5, lane = tid & 31;
    const int q0 = qt * 64;
    const size_t qg  = ((size_t)(b * NH_ + h) * S_ + q0) * HD_;
    const size_t kvg = ((size_t)(b * NKV_ + kvh) * S_) * HD_;

    // Q load (hi/lo)
#pragma unroll
    for (int u = 0; u < 16; u++) {
        int c = tid + u * 128;
        int comp = c >> 10, r = (c >> 4) & 63, ch = c & 15;
        const __half* src = (comp ? Ql : Qh) + qg + (size_t)r * HD_ + ch * 8;
        CP_ASYNC16(sb + comp * FTILE + r * FROWB + ch * 16, src);
    }
    auto load_kv = [&](int t, int st) {
        uint32_t base = sb + 2 * FTILE + st * 4 * FTILE;
        size_t g = kvg + (size_t)t * 64 * HD_;
#pragma unroll
        for (int u = 0; u < 32; u++) {
            int c = tid + u * 128;
            int comp = c >> 10, r = (c >> 4) & 63, ch = c & 15;
            const __half* src = (comp == 0 ? Kh : comp == 1 ? Kl
                               : comp == 2 ? Vh : Vl) + g + (size_t)r * HD_ + ch * 8;
            CP_ASYNC16(base + comp * FTILE + r * FROWB + ch * 16, src);
        }
        CP_COMMIT();
    };
    load_kv(0, 0);                       // group0 = Q + KV0
    if (qt >= 1) load_kv(1, 1);          // group1

    float oacc[16][4];
#pragma unroll
    for (int i = 0; i < 16; i++)
#pragma unroll
        for (int r = 0; r < 4; r++) oacc[i][r] = 0.0f;
    float mrun0 = -1e30f, mrun1 = -1e30f, lrun0 = 0.0f, lrun1 = 0.0f;

    const uint32_t qa_off = (uint32_t)(wid * 16 + (lane & 15)) * FROWB + (lane >> 4) * 16;
    const uint32_t ka_off = (uint32_t)(((lane >> 4) & 1) * 8 + (lane & 7)) * FROWB
                          + ((lane >> 3) & 1) * 16;
    const uint32_t va_off = (uint32_t)(lane & 15) * FROWB + ((lane >> 4) & 1) * 16;

    for (int t = 0; t <= qt; t++) {
        if (t < qt) { CP_WAIT(1); } else { CP_WAIT(0); }
        __syncthreads();
        uint32_t kb = sb + 2 * FTILE + (t & 1) * 4 * FTILE;
        uint32_t Khs = kb, Kls = kb + FTILE, Vhs = kb + 2 * FTILE, Vls = kb + 3 * FTILE;

        // ---- S = Q K^T (3-term) ----
        float sacc[8][4];
#pragma unroll
        for (int i = 0; i < 8; i++)
#pragma unroll
            for (int r = 0; r < 4; r++) sacc[i][r] = 0.0f;

#pragma unroll
        for (int j = 0; j < 8; j++) {
            uint32_t qo = qa_off + j * 32;
            uint32_t qhf[4], qlf[4];
            LDSM4(qhf[0], qhf[1], qhf[2], qhf[3], sb + qo);
            LDSM4(qlf[0], qlf[1], qlf[2], qlf[3], sb + FTILE + qo);
#pragma unroll
            for (int p = 0; p < 4; p++) {
                uint32_t ko = ka_off + p * 16 * FROWB + j * 32;
                uint32_t khf[4], klf[4];
                LDSM4(khf[0], khf[1], khf[2], khf[3], Khs + ko);
                LDSM4(klf[0], klf[1], klf[2], klf[3], Kls + ko);
                MMA16816(sacc[2*p],   qhf, khf);
                MMA16816(sacc[2*p],   qhf, klf);
                MMA16816(sacc[2*p],   qlf, khf);
                MMA16816(sacc[2*p+1], qhf, khf + 2);
                MMA16816(sacc[2*p+1], qhf, klf + 2);
                MMA16816(sacc[2*p+1], qlf, khf + 2);
            }
        }

        // ---- softmax (online) ----
#pragma unroll
        for (int j = 0; j < 8; j++)
#pragma unroll
            for (int r = 0; r < 4; r++) sacc[j][r] *= SCALE_;

        if (t == qt) {
            int row0 = wid * 16 + (lane >> 2);
#pragma unroll
            for (int j = 0; j < 8; j++) {
                int col = 8 * j + (lane & 3) * 2;
                if (col     > row0)     sacc[j][0] = -1e30f;
                if (col + 1 > row0)     sacc[j][1] = -1e30f;
                if (col     > row0 + 8) sacc[j][2] = -1e30f;
                if (col + 1 > row0 + 8) sacc[j][3] = -1e30f;
            }
        }
        float mx0 = -1e30f, mx1 = -1e30f;
#pragma unroll
        for (int j = 0; j < 8; j++) {
            mx0 = fmaxf(mx0, fmaxf(sacc[j][0], sacc[j][1]));
            mx1 = fmaxf(mx1, fmaxf(sacc[j][2], sacc[j][3]));
        }
        mx0 = fmaxf(mx0, __shfl_xor_sync(0xffffffffu, mx0, 1));
        mx0 = fmaxf(mx0, __shfl_xor_sync(0xffffffffu, mx0, 2));
        mx1 = fmaxf(mx1, __shfl_xor_sync(0xffffffffu, mx1, 1));
        mx1 = fmaxf(mx1, __shfl_xor_sync(0xffffffffu, mx1, 2));
        float mn0 = fmaxf(mrun0, mx0), mn1 = fmaxf(mrun1, mx1);
        float al0 = __expf(mrun0 - mn0), al1 = __expf(mrun1 - mn1);

        uint32_t ph[8][2], pl[8][2];
        float l0 = 0.0f, l1 = 0.0f;
#pragma unroll
        for (int j = 0; j < 8; j++) {
            float p0 = __expf(sacc[j][0] - mn0), p1 = __expf(sacc[j][1] - mn0);
            float p2 = __expf(sacc[j][2] - mn1), p3 = __expf(sacc[j][3] - mn1);
            l0 += p0 + p1; l1 += p2 + p3;
            __half2 h01 = __floats2half2_rn(p0, p1);
            __half2 h23 = __floats2half2_rn(p2, p3);
            ph[j][0] = *(uint32_t*)&h01;
            ph[j][1] = *(uint32_t*)&h23;
            __half2 r01 = __floats2half2_rn(p0 - __low2float(h01), p1 - __high2float(h01));
            __half2 r23 = __floats2half2_rn(p2 - __low2float(h23), p3 - __high2float(h23));
            pl[j][0] = *(uint32_t*)&r01;
            pl[j][1] = *(uint32_t*)&r23;
        }
        l0 += __shfl_xor_sync(0xffffffffu, l0, 1);
        l0 += __shfl_xor_sync(0xffffffffu, l0, 2);
        l1 += __shfl_xor_sync(0xffffffffu, l1, 1);
        l1 += __shfl_xor_sync(0xffffffffu, l1, 2);
        lrun0 = lrun0 * al0 + l0; lrun1 = lrun1 * al1 + l1;
        mrun0 = mn0; mrun1 = mn1;
#pragma unroll
        for (int nt = 0; nt < 16; nt++) {
            oacc[nt][0] *= al0; oacc[nt][1] *= al0;
            oacc[nt][2] *= al1; oacc[nt][3] *= al1;
        }

        // ---- O += P V (3-term) ----
#pragma unroll
        for (int jc = 0; jc < 4; jc++) {
            uint32_t pfh[4] = {ph[2*jc][0], ph[2*jc][1], ph[2*jc+1][0], ph[2*jc+1][1]};
            uint32_t pfl[4] = {pl[2*jc][0], pl[2*jc][1], pl[2*jc+1][0], pl[2*jc+1][1]};
#pragma unroll
            for (int dp = 0; dp < 8; dp++) {
                uint32_t vo = va_off + jc * 16 * FROWB + dp * 32;
                uint32_t vhf[4], vlf[4];
                LDSM4T(vhf[0], vhf[1], vhf[2], vhf[3], Vhs + vo);
                LDSM4T(vlf[0], vlf[1], vlf[2], vlf[3], Vls + vo);
                MMA16816(oacc[2*dp],   pfh, vhf);
                MMA16816(oacc[2*dp],   pfh, vlf);
                MMA16816(oacc[2*dp],   pfl, vhf);
                MMA16816(oacc[2*dp+1], pfh, vhf + 2);
                MMA16816(oacc[2*dp+1], pfh, vlf + 2);
                MMA16816(oacc[2*dp+1], pfl, vhf + 2);
            }
        }
        __syncthreads();
        if (t + 2 <= qt) load_kv(t + 2, t & 1);
    }

    // ---- write O (fp16 hi/lo, [B*S, NH*HD]) ----
    float inv0 = 1.0f / lrun0, inv1 = 1.0f / lrun1;
    int r0 = q0 + wid * 16 + (lane >> 2);
    size_t ob0 = ((size_t)(b * S_ + r0)) * (NH_ * HD_) + h * HD_;
    size_t ob1 = ((size_t)(b * S_ + r0 + 8)) * (NH_ * HD_) + h * HD_;
#pragma unroll
    for (int nt = 0; nt < 16; nt++) {
        int col = nt * 8 + (lane & 3) * 2;
        float f0 = oacc[nt][0] * inv0, f1 = oacc[nt][1] * inv0;
        float f2 = oacc[nt][2] * inv1, f3 = oacc[nt][3] * inv1;
        __half2 h01 = __floats2half2_rn(f0, f1);
        __half2 h23 = __floats2half2_rn(f2, f3);
        __half2 l01 = __floats2half2_rn(f0 - __low2float(h01), f1 - __high2float(h01));
        __half2 l23 = __floats2half2_rn(f2 - __low2float(h23), f3 - __high2float(h23));
        *(__half2*)&Oh[ob0 + col] = h01;
        *(__half2*)&Ol[ob0 + col] = l01;
        *(__half2*)&Oh[ob1 + col] = h23;
        *(__half2*)&Ol[ob1 + col] = l23;
    }
}

// ======================= launch ==============================================
extern "C" void kernel_launch(void* const* d_in, const int* in_sizes, int n_in,
                              void* d_out, int out_size)
{
    (void)in_sizes; (void)n_in; (void)out_size;
    const float* hs = (const float*)d_in[0];
    const float* cs = (const float*)d_in[1];
    const float* sn = (const float*)d_in[2];
    const float* Wq = (const float*)d_in[4];
    const float* Wk = (const float*)d_in[5];
    const float* Wv = (const float*)d_in[6];
    const float* Wo = (const float*)d_in[7];
    float* out = (float*)d_out;

    float *q, *k, *v;
    cudaGetSymbolAddress((void**)&q, g_q);
    cudaGetSymbolAddress((void**)&k, g_k);
    cudaGetSymbolAddress((void**)&v, g_v);

    __half *hsh, *hsl, *wqh, *wql, *wkh, *wkl, *wvh, *wvl, *woh, *wol, *oh, *ol;
    __half *qh, *ql, *kh, *kl, *vh, *vl;
    cudaGetSymbolAddress((void**)&hsh, g_hs_h); cudaGetSymbolAddress((void**)&hsl, g_hs_l);
    cudaGetSymbolAddress((void**)&wqh, g_wq_h); cudaGetSymbolAddress((void**)&wql, g_wq_l);
    cudaGetSymbolAddress((void**)&wkh, g_wk_h); cudaGetSymbolAddress((void**)&wkl, g_wk_l);
    cudaGetSymbolAddress((void**)&wvh, g_wv_h); cudaGetSymbolAddress((void**)&wvl, g_wv_l);
    cudaGetSymbolAddress((void**)&woh, g_wo_h); cudaGetSymbolAddress((void**)&wol, g_wo_l);
    cudaGetSymbolAddress((void**)&oh,  g_o_h);  cudaGetSymbolAddress((void**)&ol,  g_o_l);
    cudaGetSymbolAddress((void**)&qh,  g_qh);   cudaGetSymbolAddress((void**)&ql,  g_ql);
    cudaGetSymbolAddress((void**)&kh,  g_kh);   cudaGetSymbolAddress((void**)&kl,  g_kl);
    cudaGetSymbolAddress((void**)&vh,  g_vh);   cudaGetSymbolAddress((void**)&vl,  g_vl);

    const int n_big = 4096 * 4096 / 4, n_sm = 1024 * 4096 / 4;
    split_hilo<<<(n_big + 255) / 256, 256>>>(hs, hsh, hsl, n_big);
    split_hilo<<<(n_big + 255) / 256, 256>>>(Wq, wqh, wql, n_big);
    split_hilo<<<(n_sm + 255) / 256, 256>>>(Wk, wkh, wkl, n_sm);
    split_hilo<<<(n_sm + 255) / 256, 256>>>(Wv, wvh, wvl, n_sm);
    split_hilo<<<(n_big + 255) / 256, 256>>>(Wo, woh, wol, n_big);

    cudaFuncSetAttribute(gemm3_h16<true>,
                         cudaFuncAttributeMaxDynamicSharedMemorySize, GSMEM_BYTES);
    cudaFuncSetAttribute(gemm3_h16<false>,
                         cudaFuncAttributeMaxDynamicSharedMemorySize, GSMEM_BYTES);

    gemm3_h16<true><<<dim3(32, 32), 256, GSMEM_BYTES>>>(hsh, hsl, wqh, wql, q, 4096, 4096, NH_);
    gemm3_h16<true><<<dim3(8, 32),  256, GSMEM_BYTES>>>(hsh, hsl, wkh, wkl, k, 4096, 1024, NKV_);
    gemm3_h16<true><<<dim3(8, 32),  256, GSMEM_BYTES>>>(hsh, hsl, wvh, wvl, v, 4096, 1024, NKV_);

    // RoPE -> fp16 hi/lo in head layout; V straight split
    rope_split<<<dim3(S_, NH_, B_),  128>>>(q, cs, sn, qh, ql, NH_);
    rope_split<<<dim3(S_, NKV_, B_), 128>>>(k, cs, sn, kh, kl, NKV_);
    split_hilo<<<(n_sm + 255) / 256, 256>>>(v, vh, vl, n_sm);

    cudaFuncSetAttribute(flash16,
                         cudaFuncAttributeMaxDynamicSharedMemorySize, FSMEM_BYTES);
    flash16<<<dim3(S_ / 64, NH_, B_), 128, FSMEM_BYTES>>>(qh, ql, kh, kl, vh, vl, oh, ol);

    gemm3_h16<false><<<dim3(32, 32), 256, GSMEM_BYTES>>>(oh, ol, woh, wol, out, 4096, 4096, 0);
}

// round 7
// speedup vs baseline: 2.3789x; 1.1346x over previous
#include <cuda_runtime.h>
#include <cuda_fp16.h>
#include <math.h>
#include <stdint.h>

#define B_    2
#define S_    2048
#define HID_  4096
#define NH_   32
#define NKV_  8
#define HD_   128
#define SCALE_ 0.08838834764831845f   // 128^-0.5

// ======================= PTX helpers ========================================
__device__ __forceinline__ uint32_t smem_u32(const void* p) {
    uint32_t a;
    asm("{ .reg .u64 t; cvta.to.shared.u64 t, %1; cvt.u32.u64 %0, t; }"
        : "=r"(a) : "l"(p));
    return a;
}
#define CP_ASYNC16(dst, src) \
    asm volatile("cp.async.cg.shared.global [%0], [%1], 16;" :: "r"(dst), "l"(src))
#define CP_COMMIT() asm volatile("cp.async.commit_group;" ::: "memory")
#define CP_WAIT(n)  asm volatile("cp.async.wait_group %0;" :: "n"(n) : "memory")

#define LDSM4(r0, r1, r2, r3, a)                                              \
    asm volatile("ldmatrix.sync.aligned.m8n8.x4.shared.b16 {%0,%1,%2,%3}, [%4];" \
        : "=r"(r0), "=r"(r1), "=r"(r2), "=r"(r3) : "r"(a))
#define LDSM4T(r0, r1, r2, r3, a)                                             \
    asm volatile("ldmatrix.sync.aligned.m8n8.x4.trans.shared.b16 {%0,%1,%2,%3}, [%4];" \
        : "=r"(r0), "=r"(r1), "=r"(r2), "=r"(r3) : "r"(a))

#define MMA16816(c, av, bv)                                                   \
    asm volatile("mma.sync.aligned.m16n8k16.row.col.f32.f16.f16.f32 "         \
        "{%0,%1,%2,%3}, {%4,%5,%6,%7}, {%8,%9}, {%0,%1,%2,%3};"               \
        : "+f"((c)[0]), "+f"((c)[1]), "+f"((c)[2]), "+f"((c)[3])              \
        : "r"((av)[0]), "r"((av)[1]), "r"((av)[2]), "r"((av)[3]),             \
          "r"((bv)[0]), "r"((bv)[1]))

// ======================= scratch ============================================
__device__ float g_q [B_ * NH_  * S_ * HD_];
__device__ float g_k [B_ * NKV_ * S_ * HD_];
__device__ float g_v [B_ * NKV_ * S_ * HD_];

__device__ __half g_hs_h[4096 * 4096], g_hs_l[4096 * 4096];
__device__ __half g_wq_h[4096 * 4096], g_wq_l[4096 * 4096];
__device__ __half g_wk_h[1024 * 4096], g_wk_l[1024 * 4096];
__device__ __half g_wv_h[1024 * 4096], g_wv_l[1024 * 4096];
__device__ __half g_wo_h[4096 * 4096], g_wo_l[4096 * 4096];
__device__ __half g_o_h [4096 * 4096], g_o_l [4096 * 4096];
__device__ __half g_qh[B_ * NH_  * S_ * HD_], g_ql[B_ * NH_  * S_ * HD_];
__device__ __half g_kh[B_ * NKV_ * S_ * HD_], g_kl[B_ * NKV_ * S_ * HD_];
__device__ __half g_vh[B_ * NKV_ * S_ * HD_], g_vl[B_ * NKV_ * S_ * HD_];

// ======================= split fp32 -> fp16 hi/lo ============================
__global__ void __launch_bounds__(256)
split_hilo(const float* __restrict__ x, __half* __restrict__ hi,
           __half* __restrict__ lo, int n4)
{
    int i = blockIdx.x * blockDim.x + threadIdx.x;
    if (i >= n4) return;
    float4 v = ((const float4*)x)[i];
    __half h0 = __float2half(v.x), h1 = __float2half(v.y);
    __half h2 = __float2half(v.z), h3 = __float2half(v.w);
    __half l0 = __float2half(v.x - __half2float(h0));
    __half l1 = __float2half(v.y - __half2float(h1));
    __half l2 = __float2half(v.z - __half2float(h2));
    __half l3 = __float2half(v.w - __half2float(h3));
    ((__half2*)hi)[2 * i + 0] = __halves2half2(h0, h1);
    ((__half2*)hi)[2 * i + 1] = __halves2half2(h2, h3);
    ((__half2*)lo)[2 * i + 0] = __halves2half2(l0, l1);
    ((__half2*)lo)[2 * i + 1] = __halves2half2(l2, l3);
}

// ======================= HMMA fp16x3 GEMM ====================================
// CTA 256x128, 8 warps (4m x 2n), warp tile 64x64, K-tile 32, double buffer.
#define ATILEB (256 * 80)             // 20480 B
#define BTILEB (128 * 80)             // 10240 B
#define STAGEB (2 * ATILEB + 2 * BTILEB) // 61440 B
#define GSMEM_BYTES (2 * STAGEB)      // 122880 B

template <bool HEADOUT>
__global__ void __launch_bounds__(256)
gemm3_h16(const __half* __restrict__ Ah, const __half* __restrict__ Al,
          const __half* __restrict__ Bh, const __half* __restrict__ Bl,
          float* __restrict__ C, int K, int Ntot, int H)
{
    extern __shared__ char smem[];
    const uint32_t sbase = smem_u32(smem);
    const int tid  = threadIdx.x;
    const int wid  = tid >> 5;
    const int lane = tid & 31;
    const int m0 = blockIdx.y * 256;
    const int n0 = blockIdx.x * 128;
    const int wm0 = (wid & 3) * 64;
    const int wn0 = (wid >> 2) * 64;
    const int niter = K >> 5;

    float acc[4][8][4];
#pragma unroll
    for (int i = 0; i < 4; i++)
#pragma unroll
        for (int j = 0; j < 8; j++)
#pragma unroll
            for (int r = 0; r < 4; r++) acc[i][j][r] = 0.0f;

    auto load_stage = [&](int it, int st) {
        uint32_t base = sbase + st * STAGEB;
        int kt = it << 5;
        // A hi / A lo : 256 rows x 4 segs = 1024 chunks each
#pragma unroll
        for (int u = 0; u < 4; u++) {
            int c = tid + u * 256;
            int row = c >> 2, seg = c & 3;
            uint32_t o = (uint32_t)row * 80 + seg * 16;
            size_t go = (size_t)(m0 + row) * K + kt + seg * 8;
            CP_ASYNC16(base + o,          Ah + go);
            CP_ASYNC16(base + ATILEB + o, Al + go);
        }
        // B hi / B lo : 128 rows x 4 segs = 512 chunks each
#pragma unroll
        for (int u = 0; u < 2; u++) {
            int c = tid + u * 256;
            int row = c >> 2, seg = c & 3;
            uint32_t o = (uint32_t)row * 80 + seg * 16;
            size_t go = (size_t)(n0 + row) * K + kt + seg * 8;
            CP_ASYNC16(base + 2 * ATILEB + o,          Bh + go);
            CP_ASYNC16(base + 2 * ATILEB + BTILEB + o, Bl + go);
        }
        CP_COMMIT();
    };

    const uint32_t a_off = (uint32_t)(wm0 + (lane & 15)) * 80 + (lane >> 4) * 16;
    const uint32_t b_off = (uint32_t)(wn0 + ((lane >> 4) & 1) * 8 + (lane & 7)) * 80
                         + ((lane >> 3) & 1) * 16;

    load_stage(0, 0);
    for (int it = 0; it < niter; it++) {
        if (it + 1 < niter) { load_stage(it + 1, (it + 1) & 1); CP_WAIT(1); }
        else                { CP_WAIT(0); }
        __syncthreads();

        uint32_t tb = sbase + (it & 1) * STAGEB;
        uint32_t As_h = tb, As_l = tb + ATILEB;
        uint32_t Bs_h = tb + 2 * ATILEB, Bs_l = tb + 2 * ATILEB + BTILEB;

#pragma unroll
        for (int k16 = 0; k16 < 2; k16++) {
            uint32_t kb = k16 * 32;
            uint32_t ah[4][4], al[4][4];
#pragma unroll
            for (int mt = 0; mt < 4; mt++) {
                uint32_t o = a_off + mt * 16 * 80 + kb;
                LDSM4(ah[mt][0], ah[mt][1], ah[mt][2], ah[mt][3], As_h + o);
                LDSM4(al[mt][0], al[mt][1], al[mt][2], al[mt][3], As_l + o);
            }
#pragma unroll
            for (int np = 0; np < 4; np++) {
                uint32_t o = b_off + np * 16 * 80 + kb;
                uint32_t bh[4], bl[4];
                LDSM4(bh[0], bh[1], bh[2], bh[3], Bs_h + o);
                LDSM4(bl[0], bl[1], bl[2], bl[3], Bs_l + o);
#pragma unroll
                for (int mt = 0; mt < 4; mt++) {
                    MMA16816(acc[mt][2*np],   ah[mt], bh);
                    MMA16816(acc[mt][2*np],   ah[mt], bl);
                    MMA16816(acc[mt][2*np],   al[mt], bh);
                    MMA16816(acc[mt][2*np+1], ah[mt], bh + 2);
                    MMA16816(acc[mt][2*np+1], ah[mt], bl + 2);
                    MMA16816(acc[mt][2*np+1], al[mt], bh + 2);
                }
            }
        }
        __syncthreads();
    }

#pragma unroll
    for (int mt = 0; mt < 4; mt++) {
        int r = m0 + wm0 + mt * 16 + (lane >> 2);
#pragma unroll
        for (int nt = 0; nt < 8; nt++) {
            int cl = wn0 + nt * 8 + (lane & 3) * 2;
            if (HEADOUT) {
                int b  = r >> 11;
                int s  = r & (S_ - 1);
                int hh = n0 >> 7;
                float* base = C + (((size_t)(b * H + hh)) * S_ + s) * HD_;
                *(float2*)(base + cl) = make_float2(acc[mt][nt][0], acc[mt][nt][1]);
                float* base2 = C + (((size_t)(b * H + hh)) * S_ + (s + 8)) * HD_;
                *(float2*)(base2 + cl) = make_float2(acc[mt][nt][2], acc[mt][nt][3]);
            } else {
                float* p0 = C + (size_t)r * Ntot + n0 + cl;
                *(float2*)p0 = make_float2(acc[mt][nt][0], acc[mt][nt][1]);
                float* p1 = C + (size_t)(r + 8) * Ntot + n0 + cl;
                *(float2*)p1 = make_float2(acc[mt][nt][2], acc[mt][nt][3]);
            }
        }
    }
}

// ======================= RoPE -> fp16 hi/lo ==================================
__global__ void rope_split(const float* __restrict__ in,
                           const float* __restrict__ cs,
                           const float* __restrict__ sn,
                           __half* __restrict__ oh, __half* __restrict__ ol, int H)
{
    int s = blockIdx.x, h = blockIdx.y, b = blockIdx.z;
    int d = threadIdx.x;
    size_t base = ((size_t)(b * H + h) * S_ + s) * HD_;
    float x = in[base + d];
    float other = (d < 64) ? -in[base + d + 64] : in[base + d - 64];
    size_t ci = ((size_t)b * S_ + s) * HD_ + d;
    float val = x * cs[ci] + other * sn[ci];
    __half hh = __float2half(val);
    oh[base + d] = hh;
    ol[base + d] = __float2half(val - __half2float(hh));
}

// ======================= HMMA flash attention ================================
// BQ=128 (8 warps x 16 rows), BK=64, fp16 x3 split, fp32 accum, causal.
#define FROWB 272                      // 136 halfs row stride
#define FTILE (64 * FROWB)             // 17408 B (KV tile)
#define QTILE (128 * FROWB)            // 34816 B (Q tile, per component)
#define FSMEM_BYTES (2 * QTILE + 8 * FTILE)   // 208896 B

__global__ void __launch_bounds__(256)
flash16(const __half* __restrict__ Qh, const __half* __restrict__ Ql,
        const __half* __restrict__ Kh, const __half* __restrict__ Kl,
        const __half* __restrict__ Vh, const __half* __restrict__ Vl,
        __half* __restrict__ Oh, __half* __restrict__ Ol)
{
    extern __shared__ char smc[];
    const uint32_t sb = smem_u32(smc);
    const int qt = blockIdx.x, h = blockIdx.y, b = blockIdx.z;
    const int kvh = h >> 2;
    const int tid = threadIdx.x, wid = tid >> 5, lane = tid & 31;
    const int q0 = qt * 128;
    const int tmax = 2 * qt + 1;
    const size_t qg  = ((size_t)(b * NH_ + h) * S_ + q0) * HD_;
    const size_t kvg = ((size_t)(b * NKV_ + kvh) * S_) * HD_;

    // Q load (hi/lo): 2 comps x 128 rows x 16 chunks = 4096 over 256 thr
#pragma unroll
    for (int u = 0; u < 16; u++) {
        int c = tid + u * 256;
        int comp = c >> 11, r = (c >> 4) & 127, ch = c & 15;
        const __half* src = (comp ? Ql : Qh) + qg + (size_t)r * HD_ + ch * 8;
        CP_ASYNC16(sb + comp * QTILE + r * FROWB + ch * 16, src);
    }
    auto load_kv = [&](int t, int st) {
        uint32_t base = sb + 2 * QTILE + st * 4 * FTILE;
        size_t g = kvg + (size_t)t * 64 * HD_;
#pragma unroll
        for (int u = 0; u < 16; u++) {
            int c = tid + u * 256;
            int comp = c >> 10, r = (c >> 4) & 63, ch = c & 15;
            const __half* src = (comp == 0 ? Kh : comp == 1 ? Kl
                               : comp == 2 ? Vh : Vl) + g + (size_t)r * HD_ + ch * 8;
            CP_ASYNC16(base + comp * FTILE + r * FROWB + ch * 16, src);
        }
        CP_COMMIT();
    };
    load_kv(0, 0);                       // group0 = Q + KV0
    load_kv(1, 1);                       // tmax >= 1 always

    float oacc[16][4];
#pragma unroll
    for (int i = 0; i < 16; i++)
#pragma unroll
        for (int r = 0; r < 4; r++) oacc[i][r] = 0.0f;
    float mrun0 = -1e30f, mrun1 = -1e30f, lrun0 = 0.0f, lrun1 = 0.0f;

    const uint32_t qa_off = (uint32_t)(wid * 16 + (lane & 15)) * FROWB + (lane >> 4) * 16;
    const uint32_t ka_off = (uint32_t)(((lane >> 4) & 1) * 8 + (lane & 7)) * FROWB
                          + ((lane >> 3) & 1) * 16;
    const uint32_t va_off = (uint32_t)(lane & 15) * FROWB + ((lane >> 4) & 1) * 16;

    for (int t = 0; t <= tmax; t++) {
        if (t < tmax) { CP_WAIT(1); } else { CP_WAIT(0); }
        __syncthreads();
        uint32_t kb = sb + 2 * QTILE + (t & 1) * 4 * FTILE;
        uint32_t Khs = kb, Kls = kb + FTILE, Vhs = kb + 2 * FTILE, Vls = kb + 3 * FTILE;

        // ---- S = Q K^T (3-term) ----
        float sacc[8][4];
#pragma unroll
        for (int i = 0; i < 8; i++)
#pragma unroll
            for (int r = 0; r < 4; r++) sacc[i][r] = 0.0f;

#pragma unroll
        for (int j = 0; j < 8; j++) {
            uint32_t qo = qa_off + j * 32;
            uint32_t qhf[4], qlf[4];
            LDSM4(qhf[0], qhf[1], qhf[2], qhf[3], sb + qo);
            LDSM4(qlf[0], qlf[1], qlf[2], qlf[3], sb + QTILE + qo);
#pragma unroll
            for (int p = 0; p < 4; p++) {
                uint32_t ko = ka_off + p * 16 * FROWB + j * 32;
                uint32_t khf[4], klf[4];
                LDSM4(khf[0], khf[1], khf[2], khf[3], Khs + ko);
                LDSM4(klf[0], klf[1], klf[2], klf[3], Kls + ko);
                MMA16816(sacc[2*p],   qhf, khf);
                MMA16816(sacc[2*p],   qhf, klf);
                MMA16816(sacc[2*p],   qlf, khf);
                MMA16816(sacc[2*p+1], qhf, khf + 2);
                MMA16816(sacc[2*p+1], qhf, klf + 2);
                MMA16816(sacc[2*p+1], qlf, khf + 2);
            }
        }

        // ---- softmax (online) ----
#pragma unroll
        for (int j = 0; j < 8; j++)
#pragma unroll
            for (int r = 0; r < 4; r++) sacc[j][r] *= SCALE_;

        if (t >= 2 * qt) {   // last two KV tiles need causal masking
            int rg = q0 + wid * 16 + (lane >> 2);
#pragma unroll
            for (int j = 0; j < 8; j++) {
                int cg = 64 * t + 8 * j + (lane & 3) * 2;
                if (cg     > rg)     sacc[j][0] = -1e30f;
                if (cg + 1 > rg)     sacc[j][1] = -1e30f;
                if (cg     > rg + 8) sacc[j][2] = -1e30f;
                if (cg + 1 > rg + 8) sacc[j][3] = -1e30f;
            }
        }
        float mx0 = -1e30f, mx1 = -1e30f;
#pragma unroll
        for (int j = 0; j < 8; j++) {
            mx0 = fmaxf(mx0, fmaxf(sacc[j][0], sacc[j][1]));
            mx1 = fmaxf(mx1, fmaxf(sacc[j][2], sacc[j][3]));
        }
        mx0 = fmaxf(mx0, __shfl_xor_sync(0xffffffffu, mx0, 1));
        mx0 = fmaxf(mx0, __shfl_xor_sync(0xffffffffu, mx0, 2));
        mx1 = fmaxf(mx1, __shfl_xor_sync(0xffffffffu, mx1, 1));
        mx1 = fmaxf(mx1, __shfl_xor_sync(0xffffffffu, mx1, 2));
        float mn0 = fmaxf(mrun0, mx0), mn1 = fmaxf(mrun1, mx1);
        float al0 = __expf(mrun0 - mn0), al1 = __expf(mrun1 - mn1);

        uint32_t ph[8][2], pl[8][2];
        float l0 = 0.0f, l1 = 0.0f;
#pragma unroll
        for (int j = 0; j < 8; j++) {
            float p0 = __expf(sacc[j][0] - mn0), p1 = __expf(sacc[j][1] - mn0);
            float p2 = __expf(sacc[j][2] - mn1), p3 = __expf(sacc[j][3] - mn1);
            l0 += p0 + p1; l1 += p2 + p3;
            __half2 h01 = __floats2half2_rn(p0, p1);
            __half2 h23 = __floats2half2_rn(p2, p3);
            ph[j][0] = *(uint32_t*)&h01;
            ph[j][1] = *(uint32_t*)&h23;
            __half2 r01 = __floats2half2_rn(p0 - __low2float(h01), p1 - __high2float(h01));
            __half2 r23 = __floats2half2_rn(p2 - __low2float(h23), p3 - __high2float(h23));
            pl[j][0] = *(uint32_t*)&r01;
            pl[j][1] = *(uint32_t*)&r23;
        }
        l0 += __shfl_xor_sync(0xffffffffu, l0, 1);
        l0 += __shfl_xor_sync(0xffffffffu, l0, 2);
        l1 += __shfl_xor_sync(0xffffffffu, l1, 1);
        l1 += __shfl_xor_sync(0xffffffffu, l1, 2);
        lrun0 = lrun0 * al0 + l0; lrun1 = lrun1 * al1 + l1;
        mrun0 = mn0; mrun1 = mn1;
#pragma unroll
        for (int nt = 0; nt < 16; nt++) {
            oacc[nt][0] *= al0; oacc[nt][1] *= al0;
            oacc[nt][2] *= al1; oacc[nt][3] *= al1;
        }

        // ---- O += P V (3-term) ----
#pragma unroll
        for (int jc = 0; jc < 4; jc++) {
            uint32_t pfh[4] = {ph[2*jc][0], ph[2*jc][1], ph[2*jc+1][0], ph[2*jc+1][1]};
            uint32_t pfl[4] = {pl[2*jc][0], pl[2*jc][1], pl[2*jc+1][0], pl[2*jc+1][1]};
#pragma unroll
            for (int dp = 0; dp < 8; dp++) {
                uint32_t vo = va_off + jc * 16 * FROWB + dp * 32;
                uint32_t vhf[4], vlf[4];
                LDSM4T(vhf[0], vhf[1], vhf[2], vhf[3], Vhs + vo);
                LDSM4T(vlf[0], vlf[1], vlf[2], vlf[3], Vls + vo);
                MMA16816(oacc[2*dp],   pfh, vhf);
                MMA16816(oacc[2*dp],   pfh, vlf);
                MMA16816(oacc[2*dp],   pfl, vhf);
                MMA16816(oacc[2*dp+1], pfh, vhf + 2);
                MMA16816(oacc[2*dp+1], pfh, vlf + 2);
                MMA16816(oacc[2*dp+1], pfl, vhf + 2);
            }
        }
        __syncthreads();
        if (t + 2 <= tmax) load_kv(t + 2, t & 1);
    }

    // ---- write O (fp16 hi/lo, [B*S, NH*HD]) ----
    float inv0 = 1.0f / lrun0, inv1 = 1.0f / lrun1;
    int r0 = q0 + wid * 16 + (lane >> 2);
    size_t ob0 = ((size_t)(b * S_ + r0)) * (NH_ * HD_) + h * HD_;
    size_t ob1 = ((size_t)(b * S_ + r0 + 8)) * (NH_ * HD_) + h * HD_;
#pragma unroll
    for (int nt = 0; nt < 16; nt++) {
        int col = nt * 8 + (lane & 3) * 2;
        float f0 = oacc[nt][0] * inv0, f1 = oacc[nt][1] * inv0;
        float f2 = oacc[nt][2] * inv1, f3 = oacc[nt][3] * inv1;
        __half2 h01 = __floats2half2_rn(f0, f1);
        __half2 h23 = __floats2half2_rn(f2, f3);
        __half2 l01 = __floats2half2_rn(f0 - __low2float(h01), f1 - __high2float(h01));
        __half2 l23 = __floats2half2_rn(f2 - __low2float(h23), f3 - __high2float(h23));
        *(__half2*)&Oh[ob0 + col] = h01;
        *(__half2*)&Ol[ob0 + col] = l01;
        *(__half2*)&Oh[ob1 + col] = h23;
        *(__half2*)&Ol[ob1 + col] = l23;
    }
}

// ======================= launch ==============================================
extern "C" void kernel_launch(void* const* d_in, const int* in_sizes, int n_in,
                              void* d_out, int out_size)
{
    (void)in_sizes; (void)n_in; (void)out_size;
    const float* hs = (const float*)d_in[0];
    const float* cs = (const float*)d_in[1];
    const float* sn = (const float*)d_in[2];
    const float* Wq = (const float*)d_in[4];
    const float* Wk = (const float*)d_in[5];
    const float* Wv = (const float*)d_in[6];
    const float* Wo = (const float*)d_in[7];
    float* out = (float*)d_out;

    float *q, *k, *v;
    cudaGetSymbolAddress((void**)&q, g_q);
    cudaGetSymbolAddress((void**)&k, g_k);
    cudaGetSymbolAddress((void**)&v, g_v);

    __half *hsh, *hsl, *wqh, *wql, *wkh, *wkl, *wvh, *wvl, *woh, *wol, *oh, *ol;
    __half *qh, *ql, *kh, *kl, *vh, *vl;
    cudaGetSymbolAddress((void**)&hsh, g_hs_h); cudaGetSymbolAddress((void**)&hsl, g_hs_l);
    cudaGetSymbolAddress((void**)&wqh, g_wq_h); cudaGetSymbolAddress((void**)&wql, g_wq_l);
    cudaGetSymbolAddress((void**)&wkh, g_wk_h); cudaGetSymbolAddress((void**)&wkl, g_wk_l);
    cudaGetSymbolAddress((void**)&wvh, g_wv_h); cudaGetSymbolAddress((void**)&wvl, g_wv_l);
    cudaGetSymbolAddress((void**)&woh, g_wo_h); cudaGetSymbolAddress((void**)&wol, g_wo_l);
    cudaGetSymbolAddress((void**)&oh,  g_o_h);  cudaGetSymbolAddress((void**)&ol,  g_o_l);
    cudaGetSymbolAddress((void**)&qh,  g_qh);   cudaGetSymbolAddress((void**)&ql,  g_ql);
    cudaGetSymbolAddress((void**)&kh,  g_kh);   cudaGetSymbolAddress((void**)&kl,  g_kl);
    cudaGetSymbolAddress((void**)&vh,  g_vh);   cudaGetSymbolAddress((void**)&vl,  g_vl);

    const int n_big = 4096 * 4096 / 4, n_sm = 1024 * 4096 / 4;
    split_hilo<<<(n_big + 255) / 256, 256>>>(hs, hsh, hsl, n_big);
    split_hilo<<<(n_big + 255) / 256, 256>>>(Wq, wqh, wql, n_big);
    split_hilo<<<(n_sm + 255) / 256, 256>>>(Wk, wkh, wkl, n_sm);
    split_hilo<<<(n_sm + 255) / 256, 256>>>(Wv, wvh, wvl, n_sm);
    split_hilo<<<(n_big + 255) / 256, 256>>>(Wo, woh, wol, n_big);

    cudaFuncSetAttribute(gemm3_h16<true>,
                         cudaFuncAttributeMaxDynamicSharedMemorySize, GSMEM_BYTES);
    cudaFuncSetAttribute(gemm3_h16<false>,
                         cudaFuncAttributeMaxDynamicSharedMemorySize, GSMEM_BYTES);

    // projections: C = A @ W^T  (M=4096 in 256-tiles, N in 128-tiles)
    gemm3_h16<true><<<dim3(32, 16), 256, GSMEM_BYTES>>>(hsh, hsl, wqh, wql, q, 4096, 4096, NH_);
    gemm3_h16<true><<<dim3(8, 16),  256, GSMEM_BYTES>>>(hsh, hsl, wkh, wkl, k, 4096, 1024, NKV_);
    gemm3_h16<true><<<dim3(8, 16),  256, GSMEM_BYTES>>>(hsh, hsl, wvh, wvl, v, 4096, 1024, NKV_);

    rope_split<<<dim3(S_, NH_, B_),  128>>>(q, cs, sn, qh, ql, NH_);
    rope_split<<<dim3(S_, NKV_, B_), 128>>>(k, cs, sn, kh, kl, NKV_);
    split_hilo<<<(n_sm + 255) / 256, 256>>>(v, vh, vl, n_sm);

    cudaFuncSetAttribute(flash16,
                         cudaFuncAttributeMaxDynamicSharedMemorySize, FSMEM_BYTES);
    flash16<<<dim3(S_ / 128, NH_, B_), 256, FSMEM_BYTES>>>(qh, ql, kh, kl, vh, vl, oh, ol);

    gemm3_h16<false><<<dim3(32, 16), 256, GSMEM_BYTES>>>(oh, ol, woh, wol, out, 4096, 4096, 0);
}

// round 8
// speedup vs baseline: 2.5768x; 1.0832x over previous
#include <cuda_runtime.h>
#include <cuda_fp16.h>
#include <math.h>
#include <stdint.h>

#define B_    2
#define S_    2048
#define HID_  4096
#define NH_   32
#define NKV_  8
#define HD_   128
#define SCALE_ 0.08838834764831845f   // 128^-0.5

// ======================= PTX helpers ========================================
__device__ __forceinline__ uint32_t smem_u32(const void* p) {
    uint32_t a;
    asm("{ .reg .u64 t; cvta.to.shared.u64 t, %1; cvt.u32.u64 %0, t; }"
        : "=r"(a) : "l"(p));
    return a;
}
#define CP_ASYNC16(dst, src) \
    asm volatile("cp.async.cg.shared.global [%0], [%1], 16;" :: "r"(dst), "l"(src))
#define CP_COMMIT() asm volatile("cp.async.commit_group;" ::: "memory")
#define CP_WAIT(n)  asm volatile("cp.async.wait_group %0;" :: "n"(n) : "memory")

#define LDSM4(r0, r1, r2, r3, a)                                              \
    asm volatile("ldmatrix.sync.aligned.m8n8.x4.shared.b16 {%0,%1,%2,%3}, [%4];" \
        : "=r"(r0), "=r"(r1), "=r"(r2), "=r"(r3) : "r"(a))
#define LDSM4T(r0, r1, r2, r3, a)                                             \
    asm volatile("ldmatrix.sync.aligned.m8n8.x4.trans.shared.b16 {%0,%1,%2,%3}, [%4];" \
        : "=r"(r0), "=r"(r1), "=r"(r2), "=r"(r3) : "r"(a))

#define MMA16816(c, av, bv)                                                   \
    asm volatile("mma.sync.aligned.m16n8k16.row.col.f32.f16.f16.f32 "         \
        "{%0,%1,%2,%3}, {%4,%5,%6,%7}, {%8,%9}, {%0,%1,%2,%3};"               \
        : "+f"((c)[0]), "+f"((c)[1]), "+f"((c)[2]), "+f"((c)[3])              \
        : "r"((av)[0]), "r"((av)[1]), "r"((av)[2]), "r"((av)[3]),             \
          "r"((bv)[0]), "r"((bv)[1]))

// ======================= scratch ============================================
__device__ __half g_hs_h[4096 * 4096], g_hs_l[4096 * 4096];
__device__ __half g_wq_h[4096 * 4096], g_wq_l[4096 * 4096];
__device__ __half g_wk_h[1024 * 4096], g_wk_l[1024 * 4096];
__device__ __half g_wv_h[1024 * 4096], g_wv_l[1024 * 4096];
__device__ __half g_wo_h[4096 * 4096], g_wo_l[4096 * 4096];
__device__ __half g_o_h [4096 * 4096], g_o_l [4096 * 4096];
// projection outputs (pre-rope), head layout [B,H,S,HD]
__device__ __half g_qh [B_ * NH_  * S_ * HD_], g_ql [B_ * NH_  * S_ * HD_];
__device__ __half g_kh [B_ * NKV_ * S_ * HD_], g_kl [B_ * NKV_ * S_ * HD_];
__device__ __half g_vh [B_ * NKV_ * S_ * HD_], g_vl [B_ * NKV_ * S_ * HD_];
// rope'd
__device__ __half g_qrh[B_ * NH_  * S_ * HD_], g_qrl[B_ * NH_  * S_ * HD_];
__device__ __half g_krh[B_ * NKV_ * S_ * HD_], g_krl[B_ * NKV_ * S_ * HD_];

// ======================= split fp32 -> fp16 hi/lo ============================
__global__ void __launch_bounds__(256)
split_hilo(const float* __restrict__ x, __half* __restrict__ hi,
           __half* __restrict__ lo, int n4)
{
    int i = blockIdx.x * blockDim.x + threadIdx.x;
    if (i >= n4) return;
    float4 v = ((const float4*)x)[i];
    __half h0 = __float2half(v.x), h1 = __float2half(v.y);
    __half h2 = __float2half(v.z), h3 = __float2half(v.w);
    __half l0 = __float2half(v.x - __half2float(h0));
    __half l1 = __float2half(v.y - __half2float(h1));
    __half l2 = __float2half(v.z - __half2float(h2));
    __half l3 = __float2half(v.w - __half2float(h3));
    ((__half2*)hi)[2 * i + 0] = __halves2half2(h0, h1);
    ((__half2*)hi)[2 * i + 1] = __halves2half2(h2, h3);
    ((__half2*)lo)[2 * i + 0] = __halves2half2(l0, l1);
    ((__half2*)lo)[2 * i + 1] = __halves2half2(l2, l3);
}

// ======================= HMMA fp16x3 GEMM ====================================
// CTA 256x128, 8 warps (4m x 2n), warp tile 64x64, K-tile 64, double buffer.
// MODE 0: C fp32 flat [M, Ntot]
// MODE 2: fused QKV — per-blockIdx.x B select, hi/lo fp16 out in head layout
#define ROWB  144                     // 72 halfs row stride (64 data + 8 pad)
#define ATILEB (256 * ROWB)           // 36864 B
#define BTILEB (128 * ROWB)           // 18432 B
#define STAGEB (2 * ATILEB + 2 * BTILEB) // 110592 B
#define GSMEM_BYTES (2 * STAGEB)      // 221184 B

template <int MODE>
__global__ void __launch_bounds__(256)
gemm3_h16(const __half* __restrict__ Ah, const __half* __restrict__ Al,
          const __half* __restrict__ Bqh, const __half* __restrict__ Bql,
          const __half* __restrict__ Bkh, const __half* __restrict__ Bkl,
          const __half* __restrict__ Bvh, const __half* __restrict__ Bvl,
          float* __restrict__ C, int K, int Ntot,
          __half* __restrict__ Qh, __half* __restrict__ Ql,
          __half* __restrict__ Kh, __half* __restrict__ Kl,
          __half* __restrict__ Vh, __half* __restrict__ Vl)
{
    extern __shared__ char smem[];
    const uint32_t sbase = smem_u32(smem);
    const int tid  = threadIdx.x;
    const int wid  = tid >> 5;
    const int lane = tid & 31;
    const int bx = blockIdx.x;
    const int m0 = blockIdx.y * 256;
    const int wm0 = (wid & 3) * 64;
    const int wn0 = (wid >> 2) * 64;
    const int niter = K >> 6;

    // select B operand + output target
    const __half *Bh_, *Bl_;
    int n0;          // row offset into the selected B matrix
    if (MODE == 2) {
        if (bx < 32)      { Bh_ = Bqh; Bl_ = Bql; n0 = bx * 128; }
        else if (bx < 40) { Bh_ = Bkh; Bl_ = Bkl; n0 = (bx - 32) * 128; }
        else              { Bh_ = Bvh; Bl_ = Bvl; n0 = (bx - 40) * 128; }
    } else {
        Bh_ = Bqh; Bl_ = Bql; n0 = bx * 128;
    }

    float acc[4][8][4];
#pragma unroll
    for (int i = 0; i < 4; i++)
#pragma unroll
        for (int j = 0; j < 8; j++)
#pragma unroll
            for (int r = 0; r < 4; r++) acc[i][j][r] = 0.0f;

    auto load_stage = [&](int it, int st) {
        uint32_t base = sbase + st * STAGEB;
        int kt = it << 6;
        // A hi/lo: 256 rows x 8 segs
#pragma unroll
        for (int u = 0; u < 8; u++) {
            int c = tid + u * 256;
            int row = c >> 3, seg = c & 7;
            uint32_t o = (uint32_t)row * ROWB + seg * 16;
            size_t go = (size_t)(m0 + row) * K + kt + seg * 8;
            CP_ASYNC16(base + o,          Ah + go);
            CP_ASYNC16(base + ATILEB + o, Al + go);
        }
        // B hi/lo: 128 rows x 8 segs
#pragma unroll
        for (int u = 0; u < 4; u++) {
            int c = tid + u * 256;
            int row = c >> 3, seg = c & 7;
            uint32_t o = (uint32_t)row * ROWB + seg * 16;
            size_t go = (size_t)(n0 + row) * K + kt + seg * 8;
            CP_ASYNC16(base + 2 * ATILEB + o,          Bh_ + go);
            CP_ASYNC16(base + 2 * ATILEB + BTILEB + o, Bl_ + go);
        }
        CP_COMMIT();
    };

    const uint32_t a_off = (uint32_t)(wm0 + (lane & 15)) * ROWB + (lane >> 4) * 16;
    const uint32_t b_off = (uint32_t)(wn0 + ((lane >> 4) & 1) * 8 + (lane & 7)) * ROWB
                         + ((lane >> 3) & 1) * 16;

    load_stage(0, 0);
    for (int it = 0; it < niter; it++) {
        if (it + 1 < niter) { load_stage(it + 1, (it + 1) & 1); CP_WAIT(1); }
        else                { CP_WAIT(0); }
        __syncthreads();

        uint32_t tb = sbase + (it & 1) * STAGEB;
        uint32_t As_h = tb, As_l = tb + ATILEB;
        uint32_t Bs_h = tb + 2 * ATILEB, Bs_l = tb + 2 * ATILEB + BTILEB;

#pragma unroll
        for (int k16 = 0; k16 < 4; k16++) {
            uint32_t kb = k16 * 32;
            uint32_t ah[4][4], al[4][4];
#pragma unroll
            for (int mt = 0; mt < 4; mt++) {
                uint32_t o = a_off + mt * 16 * ROWB + kb;
                LDSM4(ah[mt][0], ah[mt][1], ah[mt][2], ah[mt][3], As_h + o);
                LDSM4(al[mt][0], al[mt][1], al[mt][2], al[mt][3], As_l + o);
            }
#pragma unroll
            for (int np = 0; np < 4; np++) {
                uint32_t o = b_off + np * 16 * ROWB + kb;
                uint32_t bh[4], bl[4];
                LDSM4(bh[0], bh[1], bh[2], bh[3], Bs_h + o);
                LDSM4(bl[0], bl[1], bl[2], bl[3], Bs_l + o);
#pragma unroll
                for (int mt = 0; mt < 4; mt++) {
                    MMA16816(acc[mt][2*np],   ah[mt], bh);
                    MMA16816(acc[mt][2*np],   ah[mt], bl);
                    MMA16816(acc[mt][2*np],   al[mt], bh);
                    MMA16816(acc[mt][2*np+1], ah[mt], bh + 2);
                    MMA16816(acc[mt][2*np+1], ah[mt], bl + 2);
                    MMA16816(acc[mt][2*np+1], al[mt], bh + 2);
                }
            }
        }
        __syncthreads();
    }

    if (MODE == 2) {
        // hi/lo fp16 out in head layout [B][H][S][HD]; one n-block == one head
        __half *Oh_, *Ol_; int Hh, hh;
        if (bx < 32)      { hh = bx;      Oh_ = Qh; Ol_ = Ql; Hh = NH_; }
        else if (bx < 40) { hh = bx - 32; Oh_ = Kh; Ol_ = Kl; Hh = NKV_; }
        else              { hh = bx - 40; Oh_ = Vh; Ol_ = Vl; Hh = NKV_; }
#pragma unroll
        for (int mt = 0; mt < 4; mt++) {
            int r = m0 + wm0 + mt * 16 + (lane >> 2);
            int b  = r >> 11;
            int s  = r & (S_ - 1);
            size_t base0 = (((size_t)(b * Hh + hh)) * S_ + s) * HD_;
            size_t base1 = (((size_t)(b * Hh + hh)) * S_ + s + 8) * HD_;
#pragma unroll
            for (int nt = 0; nt < 8; nt++) {
                int cl = wn0 + nt * 8 + (lane & 3) * 2;
                float a0 = acc[mt][nt][0], a1 = acc[mt][nt][1];
                float a2 = acc[mt][nt][2], a3 = acc[mt][nt][3];
                __half2 h01 = __floats2half2_rn(a0, a1);
                __half2 h23 = __floats2half2_rn(a2, a3);
                __half2 l01 = __floats2half2_rn(a0 - __low2float(h01),
                                                a1 - __high2float(h01));
                __half2 l23 = __floats2half2_rn(a2 - __low2float(h23),
                                                a3 - __high2float(h23));
                *(__half2*)&Oh_[base0 + cl] = h01;
                *(__half2*)&Ol_[base0 + cl] = l01;
                *(__half2*)&Oh_[base1 + cl] = h23;
                *(__half2*)&Ol_[base1 + cl] = l23;
            }
        }
    } else {
#pragma unroll
        for (int mt = 0; mt < 4; mt++) {
            int r = m0 + wm0 + mt * 16 + (lane >> 2);
#pragma unroll
            for (int nt = 0; nt < 8; nt++) {
                int cl = bx * 128 + wn0 + nt * 8 + (lane & 3) * 2;
                float* p0 = C + (size_t)r * Ntot + cl;
                *(float2*)p0 = make_float2(acc[mt][nt][0], acc[mt][nt][1]);
                float* p1 = C + (size_t)(r + 8) * Ntot + cl;
                *(float2*)p1 = make_float2(acc[mt][nt][2], acc[mt][nt][3]);
            }
        }
    }
}

// ======================= RoPE on hi/lo pairs =================================
__global__ void rope_pair(const __half* __restrict__ ih, const __half* __restrict__ il,
                          const float* __restrict__ cs, const float* __restrict__ sn,
                          __half* __restrict__ oh, __half* __restrict__ ol, int H)
{
    int s = blockIdx.x, h = blockIdx.y, b = blockIdx.z;
    int d = threadIdx.x;
    size_t base = ((size_t)(b * H + h) * S_ + s) * HD_;
    float x = __half2float(ih[base + d]) + __half2float(il[base + d]);
    int dp = (d < 64) ? d + 64 : d - 64;
    float o = __half2float(ih[base + dp]) + __half2float(il[base + dp]);
    if (d < 64) o = -o;
    size_t ci = ((size_t)b * S_ + s) * HD_ + d;
    float val = x * cs[ci] + o * sn[ci];
    __half hh = __float2half(val);
    oh[base + d] = hh;
    ol[base + d] = __float2half(val - __half2float(hh));
}

// ======================= HMMA flash attention ================================
// BQ=128 (8 warps x 16 rows), BK=64, fp16 x3 split, fp32 accum, causal.
#define FROWB 272
#define FTILE (64 * FROWB)
#define QTILE (128 * FROWB)
#define FSMEM_BYTES (2 * QTILE + 8 * FTILE)

__global__ void __launch_bounds__(256)
flash16(const __half* __restrict__ Qh, const __half* __restrict__ Ql,
        const __half* __restrict__ Kh, const __half* __restrict__ Kl,
        const __half* __restrict__ Vh, const __half* __restrict__ Vl,
        __half* __restrict__ Oh, __half* __restrict__ Ol)
{
    extern __shared__ char smc[];
    const uint32_t sb = smem_u32(smc);
    const int qt = blockIdx.x, h = blockIdx.y, b = blockIdx.z;
    const int kvh = h >> 2;
    const int tid = threadIdx.x, wid = tid >> 5, lane = tid & 31;
    const int q0 = qt * 128;
    const int tmax = 2 * qt + 1;
    const size_t qg  = ((size_t)(b * NH_ + h) * S_ + q0) * HD_;
    const size_t kvg = ((size_t)(b * NKV_ + kvh) * S_) * HD_;

#pragma unroll
    for (int u = 0; u < 16; u++) {
        int c = tid + u * 256;
        int comp = c >> 11, r = (c >> 4) & 127, ch = c & 15;
        const __half* src = (comp ? Ql : Qh) + qg + (size_t)r * HD_ + ch * 8;
        CP_ASYNC16(sb + comp * QTILE + r * FROWB + ch * 16, src);
    }
    auto load_kv = [&](int t, int st) {
        uint32_t base = sb + 2 * QTILE + st * 4 * FTILE;
        size_t g = kvg + (size_t)t * 64 * HD_;
#pragma unroll
        for (int u = 0; u < 16; u++) {
            int c = tid + u * 256;
            int comp = c >> 10, r = (c >> 4) & 63, ch = c & 15;
            const __half* src = (comp == 0 ? Kh : comp == 1 ? Kl
                               : comp == 2 ? Vh : Vl) + g + (size_t)r * HD_ + ch * 8;
            CP_ASYNC16(base + comp * FTILE + r * FROWB + ch * 16, src);
        }
        CP_COMMIT();
    };
    load_kv(0, 0);
    load_kv(1, 1);

    float oacc[16][4];
#pragma unroll
    for (int i = 0; i < 16; i++)
#pragma unroll
        for (int r = 0; r < 4; r++) oacc[i][r] = 0.0f;
    float mrun0 = -1e30f, mrun1 = -1e30f, lrun0 = 0.0f, lrun1 = 0.0f;

    const uint32_t qa_off = (uint32_t)(wid * 16 + (lane & 15)) * FROWB + (lane >> 4) * 16;
    const uint32_t ka_off = (uint32_t)(((lane >> 4) & 1) * 8 + (lane & 7)) * FROWB
                          + ((lane >> 3) & 1) * 16;
    const uint32_t va_off = (uint32_t)(lane & 15) * FROWB + ((lane >> 4) & 1) * 16;

    for (int t = 0; t <= tmax; t++) {
        if (t < tmax) { CP_WAIT(1); } else { CP_WAIT(0); }
        __syncthreads();
        uint32_t kb = sb + 2 * QTILE + (t & 1) * 4 * FTILE;
        uint32_t Khs = kb, Kls = kb + FTILE, Vhs = kb + 2 * FTILE, Vls = kb + 3 * FTILE;

        float sacc[8][4];
#pragma unroll
        for (int i = 0; i < 8; i++)
#pragma unroll
            for (int r = 0; r < 4; r++) sacc[i][r] = 0.0f;

#pragma unroll
        for (int j = 0; j < 8; j++) {
            uint32_t qo = qa_off + j * 32;
            uint32_t qhf[4], qlf[4];
            LDSM4(qhf[0], qhf[1], qhf[2], qhf[3], sb + qo);
            LDSM4(qlf[0], qlf[1], qlf[2], qlf[3], sb + QTILE + qo);
#pragma unroll
            for (int p = 0; p < 4; p++) {
                uint32_t ko = ka_off + p * 16 * FROWB + j * 32;
                uint32_t khf[4], klf[4];
                LDSM4(khf[0], khf[1], khf[2], khf[3], Khs + ko);
                LDSM4(klf[0], klf[1], klf[2], klf[3], Kls + ko);
                MMA16816(sacc[2*p],   qhf, khf);
                MMA16816(sacc[2*p],   qhf, klf);
                MMA16816(sacc[2*p],   qlf, khf);
                MMA16816(sacc[2*p+1], qhf, khf + 2);
                MMA16816(sacc[2*p+1], qhf, klf + 2);
                MMA16816(sacc[2*p+1], qlf, khf + 2);
            }
        }

#pragma unroll
        for (int j = 0; j < 8; j++)
#pragma unroll
            for (int r = 0; r < 4; r++) sacc[j][r] *= SCALE_;

        if (t >= 2 * qt) {
            int rg = q0 + wid * 16 + (lane >> 2);
#pragma unroll
            for (int j = 0; j < 8; j++) {
                int cg = 64 * t + 8 * j + (lane & 3) * 2;
                if (cg     > rg)     sacc[j][0] = -1e30f;
                if (cg + 1 > rg)     sacc[j][1] = -1e30f;
                if (cg     > rg + 8) sacc[j][2] = -1e30f;
                if (cg + 1 > rg + 8) sacc[j][3] = -1e30f;
            }
        }
        float mx0 = -1e30f, mx1 = -1e30f;
#pragma unroll
        for (int j = 0; j < 8; j++) {
            mx0 = fmaxf(mx0, fmaxf(sacc[j][0], sacc[j][1]));
            mx1 = fmaxf(mx1, fmaxf(sacc[j][2], sacc[j][3]));
        }
        mx0 = fmaxf(mx0, __shfl_xor_sync(0xffffffffu, mx0, 1));
        mx0 = fmaxf(mx0, __shfl_xor_sync(0xffffffffu, mx0, 2));
        mx1 = fmaxf(mx1, __shfl_xor_sync(0xffffffffu, mx1, 1));
        mx1 = fmaxf(mx1, __shfl_xor_sync(0xffffffffu, mx1, 2));
        float mn0 = fmaxf(mrun0, mx0), mn1 = fmaxf(mrun1, mx1);
        float al0 = __expf(mrun0 - mn0), al1 = __expf(mrun1 - mn1);

        uint32_t ph[8][2], pl[8][2];
        float l0 = 0.0f, l1 = 0.0f;
#pragma unroll
        for (int j = 0; j < 8; j++) {
            float p0 = __expf(sacc[j][0] - mn0), p1 = __expf(sacc[j][1] - mn0);
            float p2 = __expf(sacc[j][2] - mn1), p3 = __expf(sacc[j][3] - mn1);
            l0 += p0 + p1; l1 += p2 + p3;
            __half2 h01 = __floats2half2_rn(p0, p1);
            __half2 h23 = __floats2half2_rn(p2, p3);
            ph[j][0] = *(uint32_t*)&h01;
            ph[j][1] = *(uint32_t*)&h23;
            __half2 r01 = __floats2half2_rn(p0 - __low2float(h01), p1 - __high2float(h01));
            __half2 r23 = __floats2half2_rn(p2 - __low2float(h23), p3 - __high2float(h23));
            pl[j][0] = *(uint32_t*)&r01;
            pl[j][1] = *(uint32_t*)&r23;
        }
        l0 += __shfl_xor_sync(0xffffffffu, l0, 1);
        l0 += __shfl_xor_sync(0xffffffffu, l0, 2);
        l1 += __shfl_xor_sync(0xffffffffu, l1, 1);
        l1 += __shfl_xor_sync(0xffffffffu, l1, 2);
        lrun0 = lrun0 * al0 + l0; lrun1 = lrun1 * al1 + l1;
        mrun0 = mn0; mrun1 = mn1;
#pragma unroll
        for (int nt = 0; nt < 16; nt++) {
            oacc[nt][0] *= al0; oacc[nt][1] *= al0;
            oacc[nt][2] *= al1; oacc[nt][3] *= al1;
        }

#pragma unroll
        for (int jc = 0; jc < 4; jc++) {
            uint32_t pfh[4] = {ph[2*jc][0], ph[2*jc][1], ph[2*jc+1][0], ph[2*jc+1][1]};
            uint32_t pfl[4] = {pl[2*jc][0], pl[2*jc][1], pl[2*jc+1][0], pl[2*jc+1][1]};
#pragma unroll
            for (int dp = 0; dp < 8; dp++) {
                uint32_t vo = va_off + jc * 16 * FROWB + dp * 32;
                uint32_t vhf[4], vlf[4];
                LDSM4T(vhf[0], vhf[1], vhf[2], vhf[3], Vhs + vo);
                LDSM4T(vlf[0], vlf[1], vlf[2], vlf[3], Vls + vo);
                MMA16816(oacc[2*dp],   pfh, vhf);
                MMA16816(oacc[2*dp],   pfh, vlf);
                MMA16816(oacc[2*dp],   pfl, vhf);
                MMA16816(oacc[2*dp+1], pfh, vhf + 2);
                MMA16816(oacc[2*dp+1], pfh, vlf + 2);
                MMA16816(oacc[2*dp+1], pfl, vhf + 2);
            }
        }
        __syncthreads();
        if (t + 2 <= tmax) load_kv(t + 2, t & 1);
    }

    float inv0 = 1.0f / lrun0, inv1 = 1.0f / lrun1;
    int r0 = q0 + wid * 16 + (lane >> 2);
    size_t ob0 = ((size_t)(b * S_ + r0)) * (NH_ * HD_) + h * HD_;
    size_t ob1 = ((size_t)(b * S_ + r0 + 8)) * (NH_ * HD_) + h * HD_;
#pragma unroll
    for (int nt = 0; nt < 16; nt++) {
        int col = nt * 8 + (lane & 3) * 2;
        float f0 = oacc[nt][0] * inv0, f1 = oacc[nt][1] * inv0;
        float f2 = oacc[nt][2] * inv1, f3 = oacc[nt][3] * inv1;
        __half2 h01 = __floats2half2_rn(f0, f1);
        __half2 h23 = __floats2half2_rn(f2, f3);
        __half2 l01 = __floats2half2_rn(f0 - __low2float(h01), f1 - __high2float(h01));
        __half2 l23 = __floats2half2_rn(f2 - __low2float(h23), f3 - __high2float(h23));
        *(__half2*)&Oh[ob0 + col] = h01;
        *(__half2*)&Ol[ob0 + col] = l01;
        *(__half2*)&Oh[ob1 + col] = h23;
        *(__half2*)&Ol[ob1 + col] = l23;
    }
}

// ======================= launch ==============================================
extern "C" void kernel_launch(void* const* d_in, const int* in_sizes, int n_in,
                              void* d_out, int out_size)
{
    (void)in_sizes; (void)n_in; (void)out_size;
    const float* hs = (const float*)d_in[0];
    const float* cs = (const float*)d_in[1];
    const float* sn = (const float*)d_in[2];
    const float* Wq = (const float*)d_in[4];
    const float* Wk = (const float*)d_in[5];
    const float* Wv = (const float*)d_in[6];
    const float* Wo = (const float*)d_in[7];
    float* out = (float*)d_out;

    __half *hsh, *hsl, *wqh, *wql, *wkh, *wkl, *wvh, *wvl, *woh, *wol, *oh, *ol;
    __half *qh, *ql, *kh, *kl, *vh, *vl, *qrh, *qrl, *krh, *krl;
    cudaGetSymbolAddress((void**)&hsh, g_hs_h); cudaGetSymbolAddress((void**)&hsl, g_hs_l);
    cudaGetSymbolAddress((void**)&wqh, g_wq_h); cudaGetSymbolAddress((void**)&wql, g_wq_l);
    cudaGetSymbolAddress((void**)&wkh, g_wk_h); cudaGetSymbolAddress((void**)&wkl, g_wk_l);
    cudaGetSymbolAddress((void**)&wvh, g_wv_h); cudaGetSymbolAddress((void**)&wvl, g_wv_l);
    cudaGetSymbolAddress((void**)&woh, g_wo_h); cudaGetSymbolAddress((void**)&wol, g_wo_l);
    cudaGetSymbolAddress((void**)&oh,  g_o_h);  cudaGetSymbolAddress((void**)&ol,  g_o_l);
    cudaGetSymbolAddress((void**)&qh,  g_qh);   cudaGetSymbolAddress((void**)&ql,  g_ql);
    cudaGetSymbolAddress((void**)&kh,  g_kh);   cudaGetSymbolAddress((void**)&kl,  g_kl);
    cudaGetSymbolAddress((void**)&vh,  g_vh);   cudaGetSymbolAddress((void**)&vl,  g_vl);
    cudaGetSymbolAddress((void**)&qrh, g_qrh);  cudaGetSymbolAddress((void**)&qrl, g_qrl);
    cudaGetSymbolAddress((void**)&krh, g_krh);  cudaGetSymbolAddress((void**)&krl, g_krl);

    const int n_big = 4096 * 4096 / 4, n_sm = 1024 * 4096 / 4;
    split_hilo<<<(n_big + 255) / 256, 256>>>(hs, hsh, hsl, n_big);
    split_hilo<<<(n_big + 255) / 256, 256>>>(Wq, wqh, wql, n_big);
    split_hilo<<<(n_sm + 255) / 256, 256>>>(Wk, wkh, wkl, n_sm);
    split_hilo<<<(n_sm + 255) / 256, 256>>>(Wv, wvh, wvl, n_sm);
    split_hilo<<<(n_big + 255) / 256, 256>>>(Wo, woh, wol, n_big);

    cudaFuncSetAttribute(gemm3_h16<0>,
                         cudaFuncAttributeMaxDynamicSharedMemorySize, GSMEM_BYTES);
    cudaFuncSetAttribute(gemm3_h16<2>,
                         cudaFuncAttributeMaxDynamicSharedMemorySize, GSMEM_BYTES);

    // fused QKV projection: 32 Q blocks + 8 K + 8 V, hi/lo head-layout out
    gemm3_h16<2><<<dim3(48, 16), 256, GSMEM_BYTES>>>(
        hsh, hsl, wqh, wql, wkh, wkl, wvh, wvl,
        nullptr, 4096, 0, qh, ql, kh, kl, vh, vl);

    rope_pair<<<dim3(S_, NH_, B_),  128>>>(qh, ql, cs, sn, qrh, qrl, NH_);
    rope_pair<<<dim3(S_, NKV_, B_), 128>>>(kh, kl, cs, sn, krh, krl, NKV_);

    cudaFuncSetAttribute(flash16,
                         cudaFuncAttributeMaxDynamicSharedMemorySize, FSMEM_BYTES);
    flash16<<<dim3(S_ / 128, NH_, B_), 256, FSMEM_BYTES>>>(
        qrh, qrl, krh, krl, vh, vl, oh, ol);

    // output projection: fp32 flat out
    gemm3_h16<0><<<dim3(32, 16), 256, GSMEM_BYTES>>>(
        oh, ol, woh, wol, nullptr, nullptr, nullptr, nullptr,
        out, 4096, 4096, nullptr, nullptr, nullptr, nullptr, nullptr, nullptr);
}